// round 5
// baseline (speedup 1.0000x reference)
#include <cuda_runtime.h>
#include <cuda_bf16.h>
#include <cstdint>
#include <math.h>

#define BATCH 8
#define SEQ   2048
#define DIM   1024
#define BN_ROWS (BATCH * SEQ)     // 16384

// ---------------- tile config ----------------
#define TMt 128
#define TNt 128
#define TKt 64                     // bf16 per k-chunk (128B rows, SW128)

static constexpr int OFF_AH = 0;
static constexpr int OFF_AL = 16384;
static constexpr int OFF_BH = 32768;
static constexpr int OFF_BL = 49152;
static constexpr int STAGE_BYTES = 65536;
static constexpr int NSTAGE = 3;
static constexpr int SMEM_TOTAL = NSTAGE * STAGE_BYTES;  // 196608

// ---------------- scratch (__device__ globals; no allocs allowed) --------------
__device__ __nv_bfloat16 g_xh[(long long)BN_ROWS * DIM];
__device__ __nv_bfloat16 g_xl[(long long)BN_ROWS * DIM];
__device__ __nv_bfloat16 g_wth[3u * DIM * DIM];
__device__ __nv_bfloat16 g_wtl[3u * DIM * DIM];
__device__ __nv_bfloat16 g_qh[(long long)BN_ROWS * DIM];
__device__ __nv_bfloat16 g_ql[(long long)BN_ROWS * DIM];
__device__ __nv_bfloat16 g_kh[(long long)BN_ROWS * DIM];
__device__ __nv_bfloat16 g_kl[(long long)BN_ROWS * DIM];
__device__ __nv_bfloat16 g_vth[(long long)BATCH * DIM * SEQ];  // [b][dim][seq]
__device__ __nv_bfloat16 g_vtl[(long long)BATCH * DIM * SEQ];
__device__ float         g_s [(long long)BATCH * SEQ * SEQ];    // fp32 scores
__device__ __nv_bfloat16 g_ph[(long long)BATCH * SEQ * SEQ];
__device__ __nv_bfloat16 g_pl[(long long)BATCH * SEQ * SEQ];

// ---------------- PTX helpers ----------------
__device__ __forceinline__ uint32_t smem_u32(const void* p) {
    uint32_t a;
    asm("{ .reg .u64 t; cvta.to.shared.u64 t, %1; cvt.u32.u64 %0, t; }" : "=r"(a) : "l"(p));
    return a;
}
__device__ __forceinline__ void cp16(uint32_t saddr, const void* g) {
    asm volatile("cp.async.cg.shared.global [%0], [%1], 16;" :: "r"(saddr), "l"(g));
}
#define CP_COMMIT() asm volatile("cp.async.commit_group;" ::: "memory")
#define CP_WAIT1()  asm volatile("cp.async.wait_group 1;" ::: "memory")
#define CP_WAIT0()  asm volatile("cp.async.wait_group 0;" ::: "memory")

__device__ __forceinline__ void ldsm_x4(uint32_t (&r)[4], uint32_t addr) {
    asm volatile("ldmatrix.sync.aligned.m8n8.x4.shared.b16 {%0,%1,%2,%3}, [%4];"
        : "=r"(r[0]), "=r"(r[1]), "=r"(r[2]), "=r"(r[3]) : "r"(addr));
}
__device__ __forceinline__ void mma_16816(float (&d)[4], const uint32_t (&a)[4],
                                          uint32_t b0, uint32_t b1) {
    asm volatile("mma.sync.aligned.m16n8k16.row.col.f32.bf16.bf16.f32 "
        "{%0,%1,%2,%3}, {%4,%5,%6,%7}, {%8,%9}, {%0,%1,%2,%3};"
        : "+f"(d[0]), "+f"(d[1]), "+f"(d[2]), "+f"(d[3])
        : "r"(a[0]), "r"(a[1]), "r"(a[2]), "r"(a[3]), "r"(b0), "r"(b1));
}
__device__ __forceinline__ uint32_t sw128(uint32_t off) {
    return off ^ (((off >> 7) & 7) << 4);
}

// ---------------- unified split-bf16 mma.sync GEMM ----------------
// C[M,N] = (Ah+Al)[M,K] @ (Bh+Bl)[N,K]^T   (both operands K-major)
// MODE 2/3: fp32 out (scores / final)
// MODE 4  : fused QKV. blockIdx.z selects weight set/bias/output.
//           z=0 -> q (row-major split), z=1 -> k (row-major split),
//           z=2 -> v (transposed per batch via smem bounce)
template <int MODE>
__global__ __launch_bounds__(256, 1)
void gemm_bf16x3(const __nv_bfloat16* __restrict__ Ah, const __nv_bfloat16* __restrict__ Al, int lda,
                 const __nv_bfloat16* __restrict__ Bh, const __nv_bfloat16* __restrict__ Bl, int ldb,
                 const float* __restrict__ biasQ, const float* __restrict__ biasK, const float* __restrict__ biasV,
                 float* __restrict__ Fo,
                 __nv_bfloat16* __restrict__ Oqh, __nv_bfloat16* __restrict__ Oql,
                 __nv_bfloat16* __restrict__ Okh, __nv_bfloat16* __restrict__ Okl,
                 __nv_bfloat16* __restrict__ Ovh, __nv_bfloat16* __restrict__ Ovl,
                 int ldo, int K, long long sA, long long sB, long long sO)
{
    extern __shared__ __align__(1024) char smem[];
    const uint32_t smb = smem_u32(smem);
    const int tid  = threadIdx.x;
    const int lane = tid & 31;
    const int wid  = tid >> 5;
    const int wm   = wid & 3;          // 4 warps along M
    const int wn   = wid >> 2;         // 2 warps along N
    const int z = blockIdx.z;
    const int rowBase = blockIdx.y * TMt;
    const int colBase = blockIdx.x * TNt;

    const __nv_bfloat16* Ahp = Ah + sA * z + (long long)rowBase * lda;
    const __nv_bfloat16* Alp = Al + sA * z + (long long)rowBase * lda;
    const __nv_bfloat16* Bhp = Bh + sB * z + (long long)colBase * ldb;
    const __nv_bfloat16* Blp = Bl + sB * z + (long long)colBase * ldb;

    auto load_stage = [&](int st, int kt) {
        const int k0 = kt * TKt;
        const uint32_t sb = smb + st * STAGE_BYTES;
#pragma unroll
        for (int i = 0; i < 4; i++) {
            const int c  = tid + i * 256;      // 0..1023
            const int r  = c >> 3;
            const int cc = c & 7;
            const uint32_t sw = sw128((uint32_t)(r * 128 + cc * 16));
            const long long ga = (long long)r * lda + k0 + cc * 8;
            const long long gb = (long long)r * ldb + k0 + cc * 8;
            cp16(sb + OFF_AH + sw, Ahp + ga);
            cp16(sb + OFF_AL + sw, Alp + ga);
            cp16(sb + OFF_BH + sw, Bhp + gb);
            cp16(sb + OFF_BL + sw, Blp + gb);
        }
        CP_COMMIT();
    };

    float acc[2][8][4];
#pragma unroll
    for (int a = 0; a < 2; a++)
#pragma unroll
        for (int b = 0; b < 8; b++)
#pragma unroll
            for (int c = 0; c < 4; c++) acc[a][b][c] = 0.f;

    const int nk = K / TKt;
    load_stage(0, 0);
    load_stage(1, 1);

    for (int t = 0; t < nk; t++) {
        if (t + 1 < nk) { CP_WAIT1(); } else { CP_WAIT0(); }
        __syncthreads();
        if (t + 2 < nk) load_stage((t + 2) % NSTAGE, t + 2);   // issue early, overlap MMA

        const uint32_t sb = smb + (t % NSTAGE) * STAGE_BYTES;
#pragma unroll
        for (int kk = 0; kk < TKt; kk += 16) {
            uint32_t ah[2][4], al[2][4], bh[4][4], bl[4][4];
#pragma unroll
            for (int mt = 0; mt < 2; mt++) {
                const int r = wm * 32 + mt * 16 + (lane & 15);
                const uint32_t sw = sw128((uint32_t)(r * 128 + kk * 2 + ((lane >> 4) << 4)));
                ldsm_x4(ah[mt], sb + OFF_AH + sw);
                ldsm_x4(al[mt], sb + OFF_AL + sw);
            }
#pragma unroll
            for (int np = 0; np < 4; np++) {
                const int r = wn * 64 + np * 16 + (lane & 7) + ((lane >> 4) << 3);
                const uint32_t sw = sw128((uint32_t)(r * 128 + kk * 2 + (((lane >> 3) & 1) << 4)));
                ldsm_x4(bh[np], sb + OFF_BH + sw);
                ldsm_x4(bl[np], sb + OFF_BL + sw);
            }
#pragma unroll
            for (int mt = 0; mt < 2; mt++)
#pragma unroll
                for (int np = 0; np < 4; np++) {
                    mma_16816(acc[mt][np * 2 + 0], ah[mt], bh[np][0], bh[np][1]);
                    mma_16816(acc[mt][np * 2 + 0], ah[mt], bl[np][0], bl[np][1]);
                    mma_16816(acc[mt][np * 2 + 0], al[mt], bh[np][0], bh[np][1]);
                    mma_16816(acc[mt][np * 2 + 1], ah[mt], bh[np][2], bh[np][3]);
                    mma_16816(acc[mt][np * 2 + 1], ah[mt], bl[np][2], bl[np][3]);
                    mma_16816(acc[mt][np * 2 + 1], al[mt], bh[np][2], bh[np][3]);
                }
        }
        // no trailing barrier: next iteration's CP_WAIT + __syncthreads
        // protects stage reuse (stage t%3 is only rewritten at iter t+1's load of t+3)
    }

    // ---------------- epilogue ----------------
    const int mB = wm * 32;
    const int nB = wn * 64;

    const bool transposeOut = (MODE == 4) && (z == 2);

    if (!transposeOut) {
        const float* bias = (MODE == 4) ? (z == 0 ? biasQ : biasK) : nullptr;
        __nv_bfloat16* Oh = (MODE == 4) ? (z == 0 ? Oqh : Okh) : nullptr;
        __nv_bfloat16* Ol = (MODE == 4) ? (z == 0 ? Oql : Okl) : nullptr;
#pragma unroll
        for (int mt = 0; mt < 2; mt++)
#pragma unroll
            for (int nt = 0; nt < 8; nt++)
#pragma unroll
                for (int h = 0; h < 2; h++) {
                    const int m = rowBase + mB + mt * 16 + (lane >> 2) + h * 8;
                    const int n = colBase + nB + nt * 8 + ((lane & 3) << 1);
                    float v0 = acc[mt][nt][h * 2 + 0];
                    float v1 = acc[mt][nt][h * 2 + 1];
                    if (MODE == 4) {
                        v0 += __ldg(&bias[n]);
                        v1 += __ldg(&bias[n + 1]);
                        const __nv_bfloat16 h0 = __float2bfloat16(v0);
                        const __nv_bfloat16 h1 = __float2bfloat16(v1);
                        __nv_bfloat162 hv, lv;
                        hv.x = h0; hv.y = h1;
                        lv.x = __float2bfloat16(v0 - __bfloat162float(h0));
                        lv.y = __float2bfloat16(v1 - __bfloat162float(h1));
                        const long long o = (long long)m * ldo + n;
                        *(__nv_bfloat162*)(Oh + o) = hv;
                        *(__nv_bfloat162*)(Ol + o) = lv;
                    } else {
                        float2 fv; fv.x = v0; fv.y = v1;
                        *(float2*)(Fo + sO * z + (long long)m * ldo + n) = fv;
                    }
                }
    } else {
        // v^T: bounce through smem, emit coalesced per-batch [dim][seq]
        __nv_bfloat16* Th = (__nv_bfloat16*)smem;                    // [128][136]
        __nv_bfloat16* Tl = (__nv_bfloat16*)(smem + 128 * 136 * 2);
        __syncthreads();   // stage smem no longer needed
#pragma unroll
        for (int mt = 0; mt < 2; mt++)
#pragma unroll
            for (int nt = 0; nt < 8; nt++)
#pragma unroll
                for (int h = 0; h < 2; h++) {
                    const int ml = mB + mt * 16 + (lane >> 2) + h * 8;
                    const int nl = nB + nt * 8 + ((lane & 3) << 1);
#pragma unroll
                    for (int j = 0; j < 2; j++) {
                        float v = acc[mt][nt][h * 2 + j] + __ldg(&biasV[colBase + nl + j]);
                        const __nv_bfloat16 hb = __float2bfloat16(v);
                        Th[(nl + j) * 136 + ml] = hb;
                        Tl[(nl + j) * 136 + ml] = __float2bfloat16(v - __bfloat162float(hb));
                    }
                }
        __syncthreads();
        const int b   = rowBase >> 11;
        const int pos = rowBase & (SEQ - 1);
        const long long bb = (long long)b * DIM * SEQ + pos;
        for (int c = tid; c < 128 * 16; c += 256) {
            const int nr = c >> 4;
            const int cc = c & 15;
            const long long go = bb + (long long)(colBase + nr) * SEQ + cc * 8;
            *(uint4*)(Ovh + go) = *(uint4*)(Th + nr * 136 + cc * 8);
            *(uint4*)(Ovl + go) = *(uint4*)(Tl + nr * 136 + cc * 8);
        }
    }
}

// ---------------- prep kernels ----------------
__global__ void split_kernel(const float* __restrict__ src,
                             __nv_bfloat16* __restrict__ hi, __nv_bfloat16* __restrict__ lo,
                             long long n2)
{
    const long long stride = (long long)gridDim.x * blockDim.x;
    for (long long i = (long long)blockIdx.x * blockDim.x + threadIdx.x; i < n2; i += stride) {
        const float2 a = ((const float2*)src)[i];
        __nv_bfloat162 h, l;
        h.x = __float2bfloat16(a.x);
        h.y = __float2bfloat16(a.y);
        l.x = __float2bfloat16(a.x - __bfloat162float(h.x));
        l.y = __float2bfloat16(a.y - __bfloat162float(h.y));
        ((__nv_bfloat162*)hi)[i] = h;
        ((__nv_bfloat162*)lo)[i] = l;
    }
}

// transpose [DIM,DIM] fp32 W -> split bf16 Wt (Wt[n][k] = W[k][n])
__global__ void wtrans_kernel(const float* __restrict__ W,
                              __nv_bfloat16* __restrict__ Th, __nv_bfloat16* __restrict__ Tl)
{
    __shared__ float t[32][33];
    const int x = blockIdx.x * 32 + threadIdx.x;
    const int y0 = blockIdx.y * 32;
#pragma unroll
    for (int i = 0; i < 32; i += 8)
        t[threadIdx.y + i][threadIdx.x] = W[(long long)(y0 + threadIdx.y + i) * DIM + x];
    __syncthreads();
#pragma unroll
    for (int i = 0; i < 32; i += 8) {
        const float val = t[threadIdx.x][threadIdx.y + i];
        const int n = blockIdx.x * 32 + threadIdx.y + i;
        const int k = y0 + threadIdx.x;
        const __nv_bfloat16 h = __float2bfloat16(val);
        const long long o = (long long)n * DIM + k;
        Th[o] = h;
        Tl[o] = __float2bfloat16(val - __bfloat162float(h));
    }
}

// row softmax (with 1/sqrt(D) scale) -> split bf16 probs
__global__ void softmax_split_kernel(const float* __restrict__ S,
                                     __nv_bfloat16* __restrict__ Ph, __nv_bfloat16* __restrict__ Pl)
{
    const long long row = blockIdx.x;
    const float* p = S + row * (long long)SEQ;
    const int t = threadIdx.x;

    __shared__ float sh[32];
    const float scale = 0.03125f;

    float v[8];
    float mx = -INFINITY;
#pragma unroll
    for (int i = 0; i < 8; i++) {
        v[i] = p[t + i * 256] * scale;
        mx = fmaxf(mx, v[i]);
    }
#pragma unroll
    for (int o = 16; o; o >>= 1) mx = fmaxf(mx, __shfl_xor_sync(0xffffffffu, mx, o));
    if ((t & 31) == 0) sh[t >> 5] = mx;
    __syncthreads();
    if (t == 0) {
        float m = sh[0];
#pragma unroll
        for (int w = 1; w < 8; w++) m = fmaxf(m, sh[w]);
        sh[0] = m;
    }
    __syncthreads();
    mx = sh[0];

    float sum = 0.f;
#pragma unroll
    for (int i = 0; i < 8; i++) {
        v[i] = __expf(v[i] - mx);
        sum += v[i];
    }
#pragma unroll
    for (int o = 16; o; o >>= 1) sum += __shfl_xor_sync(0xffffffffu, sum, o);
    __syncthreads();
    if ((t & 31) == 0) sh[t >> 5] = sum;
    __syncthreads();
    if (t == 0) {
        float s = 0.f;
#pragma unroll
        for (int w = 0; w < 8; w++) s += sh[w];
        sh[0] = s;
    }
    __syncthreads();
    const float inv = 1.0f / sh[0];

#pragma unroll
    for (int i = 0; i < 8; i++) {
        const float pv = v[i] * inv;
        const __nv_bfloat16 h = __float2bfloat16(pv);
        const long long o = row * (long long)SEQ + t + i * 256;
        Ph[o] = h;
        Pl[o] = __float2bfloat16(pv - __bfloat162float(h));
    }
}

// ---------------- launch ----------------
extern "C" void kernel_launch(void* const* d_in, const int* in_sizes, int n_in,
                              void* d_out, int out_size)
{
    const float* x  = (const float*)d_in[0];
    const float* Wq = (const float*)d_in[1];
    const float* bq = (const float*)d_in[2];
    const float* Wk = (const float*)d_in[3];
    const float* bk = (const float*)d_in[4];
    const float* Wv = (const float*)d_in[5];
    const float* bv = (const float*)d_in[6];
    float* out = (float*)d_out;

    __nv_bfloat16 *xh, *xl, *wth, *wtl, *qh, *ql, *kh, *kl, *vth, *vtl, *ph, *pl;
    float* s;
    cudaGetSymbolAddress((void**)&xh,  g_xh);
    cudaGetSymbolAddress((void**)&xl,  g_xl);
    cudaGetSymbolAddress((void**)&wth, g_wth);
    cudaGetSymbolAddress((void**)&wtl, g_wtl);
    cudaGetSymbolAddress((void**)&qh,  g_qh);
    cudaGetSymbolAddress((void**)&ql,  g_ql);
    cudaGetSymbolAddress((void**)&kh,  g_kh);
    cudaGetSymbolAddress((void**)&kl,  g_kl);
    cudaGetSymbolAddress((void**)&vth, g_vth);
    cudaGetSymbolAddress((void**)&vtl, g_vtl);
    cudaGetSymbolAddress((void**)&s,   g_s);
    cudaGetSymbolAddress((void**)&ph,  g_ph);
    cudaGetSymbolAddress((void**)&pl,  g_pl);

    cudaFuncSetAttribute(gemm_bf16x3<2>, cudaFuncAttributeMaxDynamicSharedMemorySize, SMEM_TOTAL);
    cudaFuncSetAttribute(gemm_bf16x3<3>, cudaFuncAttributeMaxDynamicSharedMemorySize, SMEM_TOTAL);
    cudaFuncSetAttribute(gemm_bf16x3<4>, cudaFuncAttributeMaxDynamicSharedMemorySize, SMEM_TOTAL);

    // prep: split x, transpose+split weights
    split_kernel<<<4096, 256>>>(x, xh, xl, (long long)BN_ROWS * DIM / 2);
    {
        dim3 g(DIM / 32, DIM / 32), b(32, 8);
        wtrans_kernel<<<g, b>>>(Wq, wth, wtl);
        wtrans_kernel<<<g, b>>>(Wk, wth + (size_t)DIM * DIM, wtl + (size_t)DIM * DIM);
        wtrans_kernel<<<g, b>>>(Wv, wth + 2 * (size_t)DIM * DIM, wtl + 2 * (size_t)DIM * DIM);
    }

    const dim3 blk(256);
    const long long sQK = (long long)SEQ * DIM;
    const long long sSS = (long long)SEQ * SEQ;

    // fused QKV projections: one launch, z selects W/bias/output; x tiles L2-shared across z
    {
        dim3 g(DIM / TNt, BN_ROWS / TMt, 3);   // (8, 128, 3)
        gemm_bf16x3<4><<<g, blk, SMEM_TOTAL>>>(xh, xl, DIM, wth, wtl, DIM,
                                               bq, bk, bv, nullptr,
                                               qh, ql, kh, kl, vth, vtl,
                                               DIM, DIM, 0, (long long)DIM * DIM, 0);
    }
    // scores = Q @ K^T   (profiled launch: index 5)
    {
        dim3 g(SEQ / TNt, SEQ / TMt, BATCH);   // (16, 16, 8)
        gemm_bf16x3<2><<<g, blk, SMEM_TOTAL>>>(qh, ql, DIM, kh, kl, DIM,
                                               nullptr, nullptr, nullptr, s,
                                               nullptr, nullptr, nullptr, nullptr, nullptr, nullptr,
                                               SEQ, DIM, sQK, sQK, sSS);
    }
    // softmax + split
    softmax_split_kernel<<<BATCH * SEQ, 256>>>(s, ph, pl);
    // out = P @ V   (B = V^T, K-major, K=SEQ)
    {
        dim3 g(DIM / TNt, SEQ / TMt, BATCH);   // (8, 16, 8)
        gemm_bf16x3<3><<<g, blk, SMEM_TOTAL>>>(ph, pl, SEQ, vth, vtl, SEQ,
                                               nullptr, nullptr, nullptr, out,
                                               nullptr, nullptr, nullptr, nullptr, nullptr, nullptr,
                                               DIM, SEQ, sSS, (long long)DIM * SEQ, sQK);
    }
}

// round 6
// speedup vs baseline: 1.2182x; 1.2182x over previous
#include <cuda_runtime.h>
#include <cuda_bf16.h>
#include <cuda_fp16.h>
#include <cstdint>
#include <math.h>

#define BATCH 8
#define SEQ   2048
#define DIM   1024
#define BN_ROWS (BATCH * SEQ)     // 16384

// ---------------- tile config ----------------
#define TMt 128
#define TNt 128
#define TKt 64                     // 16-bit elems per k-chunk (128B rows, SW128)

// QKV (bf16 x3) stage layout
static constexpr int OFF_AH = 0;
static constexpr int OFF_AL = 16384;
static constexpr int OFF_BH = 32768;
static constexpr int OFF_BL = 49152;
static constexpr int STAGE3_BYTES = 65536;
// fp16 x2 stage layout
static constexpr int OFF2_AH = 0;
static constexpr int OFF2_AL = 16384;
static constexpr int OFF2_B  = 32768;
static constexpr int STAGE2_BYTES = 49152;
static constexpr int NSTAGE = 3;
static constexpr int SMEM3 = NSTAGE * STAGE3_BYTES;  // 196608
static constexpr int SMEM2 = NSTAGE * STAGE2_BYTES;  // 147456

// ---------------- scratch (__device__ globals; no allocs allowed) --------------
__device__ __nv_bfloat16 g_xh[(long long)BN_ROWS * DIM];
__device__ __nv_bfloat16 g_xl[(long long)BN_ROWS * DIM];
__device__ __nv_bfloat16 g_wth[3u * DIM * DIM];
__device__ __nv_bfloat16 g_wtl[3u * DIM * DIM];
__device__ __half g_qh[(long long)BN_ROWS * DIM];    // Q hi (fp16)
__device__ __half g_ql[(long long)BN_ROWS * DIM];    // Q lo (fp16)
__device__ __half g_k16[(long long)BN_ROWS * DIM];   // K single fp16
__device__ __half g_vt16[(long long)BATCH * DIM * SEQ];  // V^T single fp16 [b][dim][seq]
__device__ float  g_s [(long long)BATCH * SEQ * SEQ];    // fp32 scores
__device__ __half g_ph[(long long)BATCH * SEQ * SEQ];    // P hi (fp16)
__device__ __half g_pl[(long long)BATCH * SEQ * SEQ];    // P lo (fp16)

// ---------------- PTX helpers ----------------
__device__ __forceinline__ uint32_t smem_u32(const void* p) {
    uint32_t a;
    asm("{ .reg .u64 t; cvta.to.shared.u64 t, %1; cvt.u32.u64 %0, t; }" : "=r"(a) : "l"(p));
    return a;
}
__device__ __forceinline__ void cp16(uint32_t saddr, const void* g) {
    asm volatile("cp.async.cg.shared.global [%0], [%1], 16;" :: "r"(saddr), "l"(g));
}
#define CP_COMMIT() asm volatile("cp.async.commit_group;" ::: "memory")
#define CP_WAIT1()  asm volatile("cp.async.wait_group 1;" ::: "memory")
#define CP_WAIT0()  asm volatile("cp.async.wait_group 0;" ::: "memory")

__device__ __forceinline__ void ldsm_x4(uint32_t (&r)[4], uint32_t addr) {
    asm volatile("ldmatrix.sync.aligned.m8n8.x4.shared.b16 {%0,%1,%2,%3}, [%4];"
        : "=r"(r[0]), "=r"(r[1]), "=r"(r[2]), "=r"(r[3]) : "r"(addr));
}
__device__ __forceinline__ void mma_bf16(float (&d)[4], const uint32_t (&a)[4],
                                         uint32_t b0, uint32_t b1) {
    asm volatile("mma.sync.aligned.m16n8k16.row.col.f32.bf16.bf16.f32 "
        "{%0,%1,%2,%3}, {%4,%5,%6,%7}, {%8,%9}, {%0,%1,%2,%3};"
        : "+f"(d[0]), "+f"(d[1]), "+f"(d[2]), "+f"(d[3])
        : "r"(a[0]), "r"(a[1]), "r"(a[2]), "r"(a[3]), "r"(b0), "r"(b1));
}
__device__ __forceinline__ void mma_f16(float (&d)[4], const uint32_t (&a)[4],
                                        uint32_t b0, uint32_t b1) {
    asm volatile("mma.sync.aligned.m16n8k16.row.col.f32.f16.f16.f32 "
        "{%0,%1,%2,%3}, {%4,%5,%6,%7}, {%8,%9}, {%0,%1,%2,%3};"
        : "+f"(d[0]), "+f"(d[1]), "+f"(d[2]), "+f"(d[3])
        : "r"(a[0]), "r"(a[1]), "r"(a[2]), "r"(a[3]), "r"(b0), "r"(b1));
}
__device__ __forceinline__ uint32_t sw128(uint32_t off) {
    return off ^ (((off >> 7) & 7) << 4);
}

// ==================== fused QKV kernel (bf16 x3 products) ====================
// blockIdx.z: 0 -> Q (fp16 hi/lo, row-major), 1 -> K (fp16 single, row-major),
//             2 -> V (fp16 single, transposed per batch via smem bounce)
__global__ __launch_bounds__(256, 1)
void qkv_kernel(const __nv_bfloat16* __restrict__ Ah, const __nv_bfloat16* __restrict__ Al,
                const __nv_bfloat16* __restrict__ Bh, const __nv_bfloat16* __restrict__ Bl,
                const float* __restrict__ biasQ, const float* __restrict__ biasK, const float* __restrict__ biasV,
                __half* __restrict__ Oqh, __half* __restrict__ Oql,
                __half* __restrict__ Ok, __half* __restrict__ Ov)
{
    extern __shared__ __align__(1024) char smem[];
    const uint32_t smb = smem_u32(smem);
    const int tid  = threadIdx.x;
    const int lane = tid & 31;
    const int wid  = tid >> 5;
    const int wm   = wid & 3;
    const int wn   = wid >> 2;
    const int z = blockIdx.z;
    const int rowBase = blockIdx.y * TMt;
    const int colBase = blockIdx.x * TNt;
    const int lda = DIM, ldb = DIM;

    const __nv_bfloat16* Ahp = Ah + (long long)rowBase * lda;
    const __nv_bfloat16* Alp = Al + (long long)rowBase * lda;
    const __nv_bfloat16* Bhp = Bh + (long long)z * DIM * DIM + (long long)colBase * ldb;
    const __nv_bfloat16* Blp = Bl + (long long)z * DIM * DIM + (long long)colBase * ldb;

    auto load_stage = [&](int st, int kt) {
        const int k0 = kt * TKt;
        const uint32_t sb = smb + st * STAGE3_BYTES;
#pragma unroll
        for (int i = 0; i < 4; i++) {
            const int c  = tid + i * 256;
            const int r  = c >> 3;
            const int cc = c & 7;
            const uint32_t sw = sw128((uint32_t)(r * 128 + cc * 16));
            const long long ga = (long long)r * lda + k0 + cc * 8;
            const long long gb = (long long)r * ldb + k0 + cc * 8;
            cp16(sb + OFF_AH + sw, Ahp + ga);
            cp16(sb + OFF_AL + sw, Alp + ga);
            cp16(sb + OFF_BH + sw, Bhp + gb);
            cp16(sb + OFF_BL + sw, Blp + gb);
        }
        CP_COMMIT();
    };

    float acc[2][8][4];
#pragma unroll
    for (int a = 0; a < 2; a++)
#pragma unroll
        for (int b = 0; b < 8; b++)
#pragma unroll
            for (int c = 0; c < 4; c++) acc[a][b][c] = 0.f;

    const int nk = DIM / TKt;   // 16
    load_stage(0, 0);
    load_stage(1, 1);

    for (int t = 0; t < nk; t++) {
        if (t + 1 < nk) { CP_WAIT1(); } else { CP_WAIT0(); }
        __syncthreads();
        if (t + 2 < nk) load_stage((t + 2) % NSTAGE, t + 2);

        const uint32_t sb = smb + (t % NSTAGE) * STAGE3_BYTES;
#pragma unroll
        for (int kk = 0; kk < TKt; kk += 16) {
            uint32_t ah[2][4], al[2][4], bh[4][4], bl[4][4];
#pragma unroll
            for (int mt = 0; mt < 2; mt++) {
                const int r = wm * 32 + mt * 16 + (lane & 15);
                const uint32_t sw = sw128((uint32_t)(r * 128 + kk * 2 + ((lane >> 4) << 4)));
                ldsm_x4(ah[mt], sb + OFF_AH + sw);
                ldsm_x4(al[mt], sb + OFF_AL + sw);
            }
#pragma unroll
            for (int np = 0; np < 4; np++) {
                const int r = wn * 64 + np * 16 + (lane & 7) + ((lane >> 4) << 3);
                const uint32_t sw = sw128((uint32_t)(r * 128 + kk * 2 + (((lane >> 3) & 1) << 4)));
                ldsm_x4(bh[np], sb + OFF_BH + sw);
                ldsm_x4(bl[np], sb + OFF_BL + sw);
            }
#pragma unroll
            for (int mt = 0; mt < 2; mt++)
#pragma unroll
                for (int np = 0; np < 4; np++) {
                    mma_bf16(acc[mt][np * 2 + 0], ah[mt], bh[np][0], bh[np][1]);
                    mma_bf16(acc[mt][np * 2 + 0], ah[mt], bl[np][0], bl[np][1]);
                    mma_bf16(acc[mt][np * 2 + 0], al[mt], bh[np][0], bh[np][1]);
                    mma_bf16(acc[mt][np * 2 + 1], ah[mt], bh[np][2], bh[np][3]);
                    mma_bf16(acc[mt][np * 2 + 1], ah[mt], bl[np][2], bl[np][3]);
                    mma_bf16(acc[mt][np * 2 + 1], al[mt], bh[np][2], bh[np][3]);
                }
        }
    }

    // ---------------- epilogue ----------------
    const int mB = wm * 32;
    const int nB = wn * 64;

    if (z == 0) {
        // Q: fp16 hi/lo pair, row-major
#pragma unroll
        for (int mt = 0; mt < 2; mt++)
#pragma unroll
            for (int nt = 0; nt < 8; nt++)
#pragma unroll
                for (int h = 0; h < 2; h++) {
                    const int m = rowBase + mB + mt * 16 + (lane >> 2) + h * 8;
                    const int n = colBase + nB + nt * 8 + ((lane & 3) << 1);
                    float v0 = acc[mt][nt][h * 2 + 0] + __ldg(&biasQ[n]);
                    float v1 = acc[mt][nt][h * 2 + 1] + __ldg(&biasQ[n + 1]);
                    const __half h0 = __float2half_rn(v0);
                    const __half h1 = __float2half_rn(v1);
                    __half2 hv, lv;
                    hv.x = h0; hv.y = h1;
                    lv.x = __float2half_rn(v0 - __half2float(h0));
                    lv.y = __float2half_rn(v1 - __half2float(h1));
                    const long long o = (long long)m * DIM + n;
                    *(__half2*)(Oqh + o) = hv;
                    *(__half2*)(Oql + o) = lv;
                }
    } else if (z == 1) {
        // K: single fp16, row-major
#pragma unroll
        for (int mt = 0; mt < 2; mt++)
#pragma unroll
            for (int nt = 0; nt < 8; nt++)
#pragma unroll
                for (int h = 0; h < 2; h++) {
                    const int m = rowBase + mB + mt * 16 + (lane >> 2) + h * 8;
                    const int n = colBase + nB + nt * 8 + ((lane & 3) << 1);
                    __half2 hv;
                    hv.x = __float2half_rn(acc[mt][nt][h * 2 + 0] + __ldg(&biasK[n]));
                    hv.y = __float2half_rn(acc[mt][nt][h * 2 + 1] + __ldg(&biasK[n + 1]));
                    *(__half2*)(Ok + (long long)m * DIM + n) = hv;
                }
    } else {
        // V: single fp16, transposed per batch via smem bounce
        __half* Th = (__half*)smem;     // [128 n][136 m]
        __syncthreads();
#pragma unroll
        for (int mt = 0; mt < 2; mt++)
#pragma unroll
            for (int nt = 0; nt < 8; nt++)
#pragma unroll
                for (int h = 0; h < 2; h++) {
                    const int ml = mB + mt * 16 + (lane >> 2) + h * 8;
                    const int nl = nB + nt * 8 + ((lane & 3) << 1);
#pragma unroll
                    for (int j = 0; j < 2; j++) {
                        float v = acc[mt][nt][h * 2 + j] + __ldg(&biasV[colBase + nl + j]);
                        Th[(nl + j) * 136 + ml] = __float2half_rn(v);
                    }
                }
        __syncthreads();
        const int b   = rowBase >> 11;
        const int pos = rowBase & (SEQ - 1);
        const long long bb = (long long)b * DIM * SEQ + pos;
        for (int c = tid; c < 128 * 16; c += 256) {
            const int nr = c >> 4;
            const int cc = c & 15;
            const long long go = bb + (long long)(colBase + nr) * SEQ + cc * 8;
            *(uint4*)(Ov + go) = *(uint4*)(Th + nr * 136 + cc * 8);
        }
    }
}

// ==================== fp16 2-product GEMM ====================
// C[M,N] = (Ah+Al)[M,K] @ B[N,K]^T, fp32 out. A split fp16 (exact), B single fp16.
__global__ __launch_bounds__(256, 1)
void gemm_fp16x2(const __half* __restrict__ Ah, const __half* __restrict__ Al, int lda,
                 const __half* __restrict__ B, int ldb,
                 float* __restrict__ Fo, int ldo, int K,
                 long long sA, long long sB, long long sO)
{
    extern __shared__ __align__(1024) char smem[];
    const uint32_t smb = smem_u32(smem);
    const int tid  = threadIdx.x;
    const int lane = tid & 31;
    const int wid  = tid >> 5;
    const int wm   = wid & 3;
    const int wn   = wid >> 2;
    const int z = blockIdx.z;
    const int rowBase = blockIdx.y * TMt;
    const int colBase = blockIdx.x * TNt;

    const __half* Ahp = Ah + sA * z + (long long)rowBase * lda;
    const __half* Alp = Al + sA * z + (long long)rowBase * lda;
    const __half* Bp  = B  + sB * z + (long long)colBase * ldb;

    auto load_stage = [&](int st, int kt) {
        const int k0 = kt * TKt;
        const uint32_t sb = smb + st * STAGE2_BYTES;
#pragma unroll
        for (int i = 0; i < 4; i++) {
            const int c  = tid + i * 256;
            const int r  = c >> 3;
            const int cc = c & 7;
            const uint32_t sw = sw128((uint32_t)(r * 128 + cc * 16));
            const long long ga = (long long)r * lda + k0 + cc * 8;
            const long long gb = (long long)r * ldb + k0 + cc * 8;
            cp16(sb + OFF2_AH + sw, Ahp + ga);
            cp16(sb + OFF2_AL + sw, Alp + ga);
            cp16(sb + OFF2_B  + sw, Bp  + gb);
        }
        CP_COMMIT();
    };

    float acc[2][8][4];
#pragma unroll
    for (int a = 0; a < 2; a++)
#pragma unroll
        for (int b = 0; b < 8; b++)
#pragma unroll
            for (int c = 0; c < 4; c++) acc[a][b][c] = 0.f;

    const int nk = K / TKt;
    load_stage(0, 0);
    load_stage(1, 1);

    for (int t = 0; t < nk; t++) {
        if (t + 1 < nk) { CP_WAIT1(); } else { CP_WAIT0(); }
        __syncthreads();
        if (t + 2 < nk) load_stage((t + 2) % NSTAGE, t + 2);

        const uint32_t sb = smb + (t % NSTAGE) * STAGE2_BYTES;
#pragma unroll
        for (int kk = 0; kk < TKt; kk += 16) {
            uint32_t ah[2][4], al[2][4], bf[4][4];
#pragma unroll
            for (int mt = 0; mt < 2; mt++) {
                const int r = wm * 32 + mt * 16 + (lane & 15);
                const uint32_t sw = sw128((uint32_t)(r * 128 + kk * 2 + ((lane >> 4) << 4)));
                ldsm_x4(ah[mt], sb + OFF2_AH + sw);
                ldsm_x4(al[mt], sb + OFF2_AL + sw);
            }
#pragma unroll
            for (int np = 0; np < 4; np++) {
                const int r = wn * 64 + np * 16 + (lane & 7) + ((lane >> 4) << 3);
                const uint32_t sw = sw128((uint32_t)(r * 128 + kk * 2 + (((lane >> 3) & 1) << 4)));
                ldsm_x4(bf[np], sb + OFF2_B + sw);
            }
#pragma unroll
            for (int mt = 0; mt < 2; mt++)
#pragma unroll
                for (int np = 0; np < 4; np++) {
                    mma_f16(acc[mt][np * 2 + 0], ah[mt], bf[np][0], bf[np][1]);
                    mma_f16(acc[mt][np * 2 + 0], al[mt], bf[np][0], bf[np][1]);
                    mma_f16(acc[mt][np * 2 + 1], ah[mt], bf[np][2], bf[np][3]);
                    mma_f16(acc[mt][np * 2 + 1], al[mt], bf[np][2], bf[np][3]);
                }
        }
    }

    // fp32 epilogue
#pragma unroll
    for (int mt = 0; mt < 2; mt++)
#pragma unroll
        for (int nt = 0; nt < 8; nt++)
#pragma unroll
            for (int h = 0; h < 2; h++) {
                const int m = rowBase + wm * 32 + mt * 16 + (lane >> 2) + h * 8;
                const int n = colBase + wn * 64 + nt * 8 + ((lane & 3) << 1);
                float2 fv;
                fv.x = acc[mt][nt][h * 2 + 0];
                fv.y = acc[mt][nt][h * 2 + 1];
                *(float2*)(Fo + sO * z + (long long)m * ldo + n) = fv;
            }
}

// ---------------- prep kernels ----------------
__global__ void split_kernel(const float* __restrict__ src,
                             __nv_bfloat16* __restrict__ hi, __nv_bfloat16* __restrict__ lo,
                             long long n2)
{
    const long long stride = (long long)gridDim.x * blockDim.x;
    for (long long i = (long long)blockIdx.x * blockDim.x + threadIdx.x; i < n2; i += stride) {
        const float2 a = ((const float2*)src)[i];
        __nv_bfloat162 h, l;
        h.x = __float2bfloat16(a.x);
        h.y = __float2bfloat16(a.y);
        l.x = __float2bfloat16(a.x - __bfloat162float(h.x));
        l.y = __float2bfloat16(a.y - __bfloat162float(h.y));
        ((__nv_bfloat162*)hi)[i] = h;
        ((__nv_bfloat162*)lo)[i] = l;
    }
}

// transpose [DIM,DIM] fp32 W -> split bf16 Wt (Wt[n][k] = W[k][n])
__global__ void wtrans_kernel(const float* __restrict__ W,
                              __nv_bfloat16* __restrict__ Th, __nv_bfloat16* __restrict__ Tl)
{
    __shared__ float t[32][33];
    const int x = blockIdx.x * 32 + threadIdx.x;
    const int y0 = blockIdx.y * 32;
#pragma unroll
    for (int i = 0; i < 32; i += 8)
        t[threadIdx.y + i][threadIdx.x] = W[(long long)(y0 + threadIdx.y + i) * DIM + x];
    __syncthreads();
#pragma unroll
    for (int i = 0; i < 32; i += 8) {
        const float val = t[threadIdx.x][threadIdx.y + i];
        const int n = blockIdx.x * 32 + threadIdx.y + i;
        const int k = y0 + threadIdx.x;
        const __nv_bfloat16 h = __float2bfloat16(val);
        const long long o = (long long)n * DIM + k;
        Th[o] = h;
        Tl[o] = __float2bfloat16(val - __bfloat162float(h));
    }
}

// row softmax (with 1/sqrt(D) scale) -> fp16 hi/lo probs
__global__ void softmax_split_kernel(const float* __restrict__ S,
                                     __half* __restrict__ Ph, __half* __restrict__ Pl)
{
    const long long row = blockIdx.x;
    const float* p = S + row * (long long)SEQ;
    const int t = threadIdx.x;

    __shared__ float sh[32];
    const float scale = 0.03125f;

    float v[8];
    float mx = -INFINITY;
#pragma unroll
    for (int i = 0; i < 8; i++) {
        v[i] = p[t + i * 256] * scale;
        mx = fmaxf(mx, v[i]);
    }
#pragma unroll
    for (int o = 16; o; o >>= 1) mx = fmaxf(mx, __shfl_xor_sync(0xffffffffu, mx, o));
    if ((t & 31) == 0) sh[t >> 5] = mx;
    __syncthreads();
    if (t == 0) {
        float m = sh[0];
#pragma unroll
        for (int w = 1; w < 8; w++) m = fmaxf(m, sh[w]);
        sh[0] = m;
    }
    __syncthreads();
    mx = sh[0];

    float sum = 0.f;
#pragma unroll
    for (int i = 0; i < 8; i++) {
        v[i] = __expf(v[i] - mx);
        sum += v[i];
    }
#pragma unroll
    for (int o = 16; o; o >>= 1) sum += __shfl_xor_sync(0xffffffffu, sum, o);
    __syncthreads();
    if ((t & 31) == 0) sh[t >> 5] = sum;
    __syncthreads();
    if (t == 0) {
        float s = 0.f;
#pragma unroll
        for (int w = 0; w < 8; w++) s += sh[w];
        sh[0] = s;
    }
    __syncthreads();
    const float inv = 1.0f / sh[0];

#pragma unroll
    for (int i = 0; i < 8; i++) {
        const float pv = v[i] * inv;
        const __half h = __float2half_rn(pv);
        const long long o = row * (long long)SEQ + t + i * 256;
        Ph[o] = h;
        Pl[o] = __float2half_rn(pv - __half2float(h));
    }
}

// ---------------- launch ----------------
extern "C" void kernel_launch(void* const* d_in, const int* in_sizes, int n_in,
                              void* d_out, int out_size)
{
    const float* x  = (const float*)d_in[0];
    const float* Wq = (const float*)d_in[1];
    const float* bq = (const float*)d_in[2];
    const float* Wk = (const float*)d_in[3];
    const float* bk = (const float*)d_in[4];
    const float* Wv = (const float*)d_in[5];
    const float* bv = (const float*)d_in[6];
    float* out = (float*)d_out;

    __nv_bfloat16 *xh, *xl, *wth, *wtl;
    __half *qh, *ql, *k16, *vt16, *ph, *pl;
    float* s;
    cudaGetSymbolAddress((void**)&xh,   g_xh);
    cudaGetSymbolAddress((void**)&xl,   g_xl);
    cudaGetSymbolAddress((void**)&wth,  g_wth);
    cudaGetSymbolAddress((void**)&wtl,  g_wtl);
    cudaGetSymbolAddress((void**)&qh,   g_qh);
    cudaGetSymbolAddress((void**)&ql,   g_ql);
    cudaGetSymbolAddress((void**)&k16,  g_k16);
    cudaGetSymbolAddress((void**)&vt16, g_vt16);
    cudaGetSymbolAddress((void**)&s,    g_s);
    cudaGetSymbolAddress((void**)&ph,   g_ph);
    cudaGetSymbolAddress((void**)&pl,   g_pl);

    cudaFuncSetAttribute(qkv_kernel,  cudaFuncAttributeMaxDynamicSharedMemorySize, SMEM3);
    cudaFuncSetAttribute(gemm_fp16x2, cudaFuncAttributeMaxDynamicSharedMemorySize, SMEM2);

    // prep: split x, transpose+split weights
    split_kernel<<<4096, 256>>>(x, xh, xl, (long long)BN_ROWS * DIM / 2);
    {
        dim3 g(DIM / 32, DIM / 32), b(32, 8);
        wtrans_kernel<<<g, b>>>(Wq, wth, wtl);
        wtrans_kernel<<<g, b>>>(Wk, wth + (size_t)DIM * DIM, wtl + (size_t)DIM * DIM);
        wtrans_kernel<<<g, b>>>(Wv, wth + 2 * (size_t)DIM * DIM, wtl + 2 * (size_t)DIM * DIM);
    }

    const dim3 blk(256);
    const long long sQK = (long long)SEQ * DIM;
    const long long sSS = (long long)SEQ * SEQ;

    // fused QKV projections (bf16 x3)
    {
        dim3 g(DIM / TNt, BN_ROWS / TMt, 3);   // (8, 128, 3)
        qkv_kernel<<<g, blk, SMEM3>>>(xh, xl, wth, wtl, bq, bk, bv,
                                      qh, ql, k16, vt16);
    }
    // scores = Q @ K^T   (fp16 x2: Q split, K single)
    {
        dim3 g(SEQ / TNt, SEQ / TMt, BATCH);   // (16, 16, 8)
        gemm_fp16x2<<<g, blk, SMEM2>>>(qh, ql, DIM, k16, DIM,
                                       s, SEQ, DIM, sQK, sQK, sSS);
    }
    // softmax + fp16 split
    softmax_split_kernel<<<BATCH * SEQ, 256>>>(s, ph, pl);
    // out = P @ V   (fp16 x2: P split, V^T single; K=SEQ)
    {
        dim3 g(DIM / TNt, SEQ / TMt, BATCH);   // (8, 16, 8)
        gemm_fp16x2<<<g, blk, SMEM2>>>(ph, pl, SEQ, vt16, SEQ,
                                       out, DIM, SEQ, sSS, (long long)DIM * SEQ, sQK);
    }
}

// round 7
// speedup vs baseline: 1.4118x; 1.1589x over previous
#include <cuda_runtime.h>
#include <cuda_bf16.h>
#include <cuda_fp16.h>
#include <cstdint>
#include <math.h>

#define BATCH 8
#define SEQ   2048
#define DIM   1024
#define BN_ROWS (BATCH * SEQ)     // 16384

// ---------------- tile config ----------------
#define TMt 128
#define TNt 128
#define TKt 64                     // fp16 elems per k-chunk (128B rows, SW128)

static constexpr int OFF_AH = 0;
static constexpr int OFF_AL = 16384;
static constexpr int OFF_B  = 32768;
static constexpr int STAGE_BYTES = 49152;
static constexpr int NSTAGE = 3;
static constexpr int SMEM_TOTAL = NSTAGE * STAGE_BYTES;  // 147456

// ---------------- scratch (__device__ globals; no allocs allowed) --------------
__device__ __half g_xh[(long long)BN_ROWS * DIM];        // x hi (fp16)
__device__ __half g_xl[(long long)BN_ROWS * DIM];        // x lo (fp16)
__device__ __half g_wt16[3u * DIM * DIM];                // W^T single fp16 (q,k,v)
__device__ __half g_qh[(long long)BN_ROWS * DIM];        // Q hi
__device__ __half g_ql[(long long)BN_ROWS * DIM];        // Q lo
__device__ __half g_k16[(long long)BN_ROWS * DIM];       // K single
__device__ __half g_vt16[(long long)BATCH * DIM * SEQ];  // V^T single [b][dim][seq]
__device__ float  g_s [(long long)BATCH * SEQ * SEQ];    // fp32 scores
__device__ __half g_ph[(long long)BATCH * SEQ * SEQ];    // P hi
__device__ __half g_pl[(long long)BATCH * SEQ * SEQ];    // P lo

// ---------------- PTX helpers ----------------
__device__ __forceinline__ uint32_t smem_u32(const void* p) {
    uint32_t a;
    asm("{ .reg .u64 t; cvta.to.shared.u64 t, %1; cvt.u32.u64 %0, t; }" : "=r"(a) : "l"(p));
    return a;
}
__device__ __forceinline__ void cp16(uint32_t saddr, const void* g) {
    asm volatile("cp.async.cg.shared.global [%0], [%1], 16;" :: "r"(saddr), "l"(g));
}
#define CP_COMMIT() asm volatile("cp.async.commit_group;" ::: "memory")
#define CP_WAIT1()  asm volatile("cp.async.wait_group 1;" ::: "memory")
#define CP_WAIT0()  asm volatile("cp.async.wait_group 0;" ::: "memory")

__device__ __forceinline__ void ldsm_x4(uint32_t (&r)[4], uint32_t addr) {
    asm volatile("ldmatrix.sync.aligned.m8n8.x4.shared.b16 {%0,%1,%2,%3}, [%4];"
        : "=r"(r[0]), "=r"(r[1]), "=r"(r[2]), "=r"(r[3]) : "r"(addr));
}
__device__ __forceinline__ void mma_f16(float (&d)[4], const uint32_t (&a)[4],
                                        uint32_t b0, uint32_t b1) {
    asm volatile("mma.sync.aligned.m16n8k16.row.col.f32.f16.f16.f32 "
        "{%0,%1,%2,%3}, {%4,%5,%6,%7}, {%8,%9}, {%0,%1,%2,%3};"
        : "+f"(d[0]), "+f"(d[1]), "+f"(d[2]), "+f"(d[3])
        : "r"(a[0]), "r"(a[1]), "r"(a[2]), "r"(a[3]), "r"(b0), "r"(b1));
}
__device__ __forceinline__ uint32_t sw128(uint32_t off) {
    return off ^ (((off >> 7) & 7) << 4);
}

// ==================== unified fp16 2-product GEMM ====================
// C[M,N] = (Ah+Al)[M,K] @ B[N,K]^T, fp32 accumulate. A split fp16 (exact), B single fp16.
// MODE 0: fused QKV. z: 0 -> Q (fp16 hi/lo, row-major, +biasQ)
//                       1 -> K (fp16 single, row-major, +biasK)
//                       2 -> V (fp16 single, transposed per batch, +biasV)
// MODE 1: fp32 out (scores / final), batch via z.
template <int MODE>
__global__ __launch_bounds__(256, 1)
void gemm_fp16x2(const __half* __restrict__ Ah, const __half* __restrict__ Al, int lda,
                 const __half* __restrict__ B, int ldb,
                 const float* __restrict__ biasQ, const float* __restrict__ biasK, const float* __restrict__ biasV,
                 float* __restrict__ Fo,
                 __half* __restrict__ Oqh, __half* __restrict__ Oql,
                 __half* __restrict__ Ok, __half* __restrict__ Ov,
                 int ldo, int K, long long sA, long long sB, long long sO)
{
    extern __shared__ __align__(1024) char smem[];
    const uint32_t smb = smem_u32(smem);
    const int tid  = threadIdx.x;
    const int lane = tid & 31;
    const int wid  = tid >> 5;
    const int wm   = wid & 3;          // 4 warps along M
    const int wn   = wid >> 2;         // 2 warps along N
    const int z = blockIdx.z;
    const int rowBase = blockIdx.y * TMt;
    const int colBase = blockIdx.x * TNt;

    const __half* Ahp = Ah + sA * z + (long long)rowBase * lda;
    const __half* Alp = Al + sA * z + (long long)rowBase * lda;
    const __half* Bp  = B  + sB * z + (long long)colBase * ldb;

    auto load_stage = [&](int st, int kt) {
        const int k0 = kt * TKt;
        const uint32_t sb = smb + st * STAGE_BYTES;
#pragma unroll
        for (int i = 0; i < 4; i++) {
            const int c  = tid + i * 256;      // 0..1023
            const int r  = c >> 3;
            const int cc = c & 7;
            const uint32_t sw = sw128((uint32_t)(r * 128 + cc * 16));
            const long long ga = (long long)r * lda + k0 + cc * 8;
            const long long gb = (long long)r * ldb + k0 + cc * 8;
            cp16(sb + OFF_AH + sw, Ahp + ga);
            cp16(sb + OFF_AL + sw, Alp + ga);
            cp16(sb + OFF_B  + sw, Bp  + gb);
        }
        CP_COMMIT();
    };

    float acc[2][8][4];
#pragma unroll
    for (int a = 0; a < 2; a++)
#pragma unroll
        for (int b = 0; b < 8; b++)
#pragma unroll
            for (int c = 0; c < 4; c++) acc[a][b][c] = 0.f;

    const int nk = K / TKt;
    load_stage(0, 0);
    load_stage(1, 1);

    for (int t = 0; t < nk; t++) {
        if (t + 1 < nk) { CP_WAIT1(); } else { CP_WAIT0(); }
        __syncthreads();
        if (t + 2 < nk) load_stage((t + 2) % NSTAGE, t + 2);

        const uint32_t sb = smb + (t % NSTAGE) * STAGE_BYTES;
#pragma unroll
        for (int kk = 0; kk < TKt; kk += 16) {
            uint32_t ah[2][4], al[2][4], bf[4][4];
#pragma unroll
            for (int mt = 0; mt < 2; mt++) {
                const int r = wm * 32 + mt * 16 + (lane & 15);
                const uint32_t sw = sw128((uint32_t)(r * 128 + kk * 2 + ((lane >> 4) << 4)));
                ldsm_x4(ah[mt], sb + OFF_AH + sw);
                ldsm_x4(al[mt], sb + OFF_AL + sw);
            }
#pragma unroll
            for (int np = 0; np < 4; np++) {
                const int r = wn * 64 + np * 16 + (lane & 7) + ((lane >> 4) << 3);
                const uint32_t sw = sw128((uint32_t)(r * 128 + kk * 2 + (((lane >> 3) & 1) << 4)));
                ldsm_x4(bf[np], sb + OFF_B + sw);
            }
#pragma unroll
            for (int mt = 0; mt < 2; mt++)
#pragma unroll
                for (int np = 0; np < 4; np++) {
                    mma_f16(acc[mt][np * 2 + 0], ah[mt], bf[np][0], bf[np][1]);
                    mma_f16(acc[mt][np * 2 + 0], al[mt], bf[np][0], bf[np][1]);
                    mma_f16(acc[mt][np * 2 + 1], ah[mt], bf[np][2], bf[np][3]);
                    mma_f16(acc[mt][np * 2 + 1], al[mt], bf[np][2], bf[np][3]);
                }
        }
    }

    // ---------------- epilogue ----------------
    const int mB = wm * 32;
    const int nB = wn * 64;

    if (MODE == 1) {
#pragma unroll
        for (int mt = 0; mt < 2; mt++)
#pragma unroll
            for (int nt = 0; nt < 8; nt++)
#pragma unroll
                for (int h = 0; h < 2; h++) {
                    const int m = rowBase + mB + mt * 16 + (lane >> 2) + h * 8;
                    const int n = colBase + nB + nt * 8 + ((lane & 3) << 1);
                    float2 fv;
                    fv.x = acc[mt][nt][h * 2 + 0];
                    fv.y = acc[mt][nt][h * 2 + 1];
                    *(float2*)(Fo + sO * z + (long long)m * ldo + n) = fv;
                }
    } else if (z == 0) {
        // Q: fp16 hi/lo, row-major
#pragma unroll
        for (int mt = 0; mt < 2; mt++)
#pragma unroll
            for (int nt = 0; nt < 8; nt++)
#pragma unroll
                for (int h = 0; h < 2; h++) {
                    const int m = rowBase + mB + mt * 16 + (lane >> 2) + h * 8;
                    const int n = colBase + nB + nt * 8 + ((lane & 3) << 1);
                    float v0 = acc[mt][nt][h * 2 + 0] + __ldg(&biasQ[n]);
                    float v1 = acc[mt][nt][h * 2 + 1] + __ldg(&biasQ[n + 1]);
                    const __half h0 = __float2half_rn(v0);
                    const __half h1 = __float2half_rn(v1);
                    __half2 hv, lv;
                    hv.x = h0; hv.y = h1;
                    lv.x = __float2half_rn(v0 - __half2float(h0));
                    lv.y = __float2half_rn(v1 - __half2float(h1));
                    const long long o = (long long)m * DIM + n;
                    *(__half2*)(Oqh + o) = hv;
                    *(__half2*)(Oql + o) = lv;
                }
    } else if (z == 1) {
        // K: single fp16, row-major
#pragma unroll
        for (int mt = 0; mt < 2; mt++)
#pragma unroll
            for (int nt = 0; nt < 8; nt++)
#pragma unroll
                for (int h = 0; h < 2; h++) {
                    const int m = rowBase + mB + mt * 16 + (lane >> 2) + h * 8;
                    const int n = colBase + nB + nt * 8 + ((lane & 3) << 1);
                    __half2 hv;
                    hv.x = __float2half_rn(acc[mt][nt][h * 2 + 0] + __ldg(&biasK[n]));
                    hv.y = __float2half_rn(acc[mt][nt][h * 2 + 1] + __ldg(&biasK[n + 1]));
                    *(__half2*)(Ok + (long long)m * DIM + n) = hv;
                }
    } else {
        // V: single fp16, transposed per batch via smem bounce
        __half* Th = (__half*)smem;     // [128 n][136 m]
        __syncthreads();
#pragma unroll
        for (int mt = 0; mt < 2; mt++)
#pragma unroll
            for (int nt = 0; nt < 8; nt++)
#pragma unroll
                for (int h = 0; h < 2; h++) {
                    const int ml = mB + mt * 16 + (lane >> 2) + h * 8;
                    const int nl = nB + nt * 8 + ((lane & 3) << 1);
#pragma unroll
                    for (int j = 0; j < 2; j++) {
                        float v = acc[mt][nt][h * 2 + j] + __ldg(&biasV[colBase + nl + j]);
                        Th[(nl + j) * 136 + ml] = __float2half_rn(v);
                    }
                }
        __syncthreads();
        const int b   = rowBase >> 11;
        const int pos = rowBase & (SEQ - 1);
        const long long bb = (long long)b * DIM * SEQ + pos;
        for (int c = tid; c < 128 * 16; c += 256) {
            const int nr = c >> 4;
            const int cc = c & 15;
            const long long go = bb + (long long)(colBase + nr) * SEQ + cc * 8;
            *(uint4*)(Ov + go) = *(uint4*)(Th + nr * 136 + cc * 8);
        }
    }
}

// ---------------- prep kernels ----------------
// split fp32 -> fp16 hi + fp16 lo
__global__ void split_kernel(const float* __restrict__ src,
                             __half* __restrict__ hi, __half* __restrict__ lo,
                             long long n2)
{
    const long long stride = (long long)gridDim.x * blockDim.x;
    for (long long i = (long long)blockIdx.x * blockDim.x + threadIdx.x; i < n2; i += stride) {
        const float2 a = ((const float2*)src)[i];
        __half2 h, l;
        h.x = __float2half_rn(a.x);
        h.y = __float2half_rn(a.y);
        l.x = __float2half_rn(a.x - __half2float(h.x));
        l.y = __float2half_rn(a.y - __half2float(h.y));
        ((__half2*)hi)[i] = h;
        ((__half2*)lo)[i] = l;
    }
}

// transpose [DIM,DIM] fp32 W -> single fp16 Wt (Wt[n][k] = W[k][n])
__global__ void wtrans_kernel(const float* __restrict__ W, __half* __restrict__ T16)
{
    __shared__ float t[32][33];
    const int x = blockIdx.x * 32 + threadIdx.x;
    const int y0 = blockIdx.y * 32;
#pragma unroll
    for (int i = 0; i < 32; i += 8)
        t[threadIdx.y + i][threadIdx.x] = W[(long long)(y0 + threadIdx.y + i) * DIM + x];
    __syncthreads();
#pragma unroll
    for (int i = 0; i < 32; i += 8) {
        const float val = t[threadIdx.x][threadIdx.y + i];
        const int n = blockIdx.x * 32 + threadIdx.y + i;
        const int k = y0 + threadIdx.x;
        T16[(long long)n * DIM + k] = __float2half_rn(val);
    }
}

// row softmax (with 1/sqrt(D) scale) -> fp16 hi/lo probs
__global__ void softmax_split_kernel(const float* __restrict__ S,
                                     __half* __restrict__ Ph, __half* __restrict__ Pl)
{
    const long long row = blockIdx.x;
    const float* p = S + row * (long long)SEQ;
    const int t = threadIdx.x;

    __shared__ float sh[32];
    const float scale = 0.03125f;

    float v[8];
    float mx = -INFINITY;
#pragma unroll
    for (int i = 0; i < 8; i++) {
        v[i] = p[t + i * 256] * scale;
        mx = fmaxf(mx, v[i]);
    }
#pragma unroll
    for (int o = 16; o; o >>= 1) mx = fmaxf(mx, __shfl_xor_sync(0xffffffffu, mx, o));
    if ((t & 31) == 0) sh[t >> 5] = mx;
    __syncthreads();
    if (t == 0) {
        float m = sh[0];
#pragma unroll
        for (int w = 1; w < 8; w++) m = fmaxf(m, sh[w]);
        sh[0] = m;
    }
    __syncthreads();
    mx = sh[0];

    float sum = 0.f;
#pragma unroll
    for (int i = 0; i < 8; i++) {
        v[i] = __expf(v[i] - mx);
        sum += v[i];
    }
#pragma unroll
    for (int o = 16; o; o >>= 1) sum += __shfl_xor_sync(0xffffffffu, sum, o);
    __syncthreads();
    if ((t & 31) == 0) sh[t >> 5] = sum;
    __syncthreads();
    if (t == 0) {
        float s = 0.f;
#pragma unroll
        for (int w = 0; w < 8; w++) s += sh[w];
        sh[0] = s;
    }
    __syncthreads();
    const float inv = 1.0f / sh[0];

#pragma unroll
    for (int i = 0; i < 8; i++) {
        const float pv = v[i] * inv;
        const __half h = __float2half_rn(pv);
        const long long o = row * (long long)SEQ + t + i * 256;
        Ph[o] = h;
        Pl[o] = __float2half_rn(pv - __half2float(h));
    }
}

// ---------------- launch ----------------
extern "C" void kernel_launch(void* const* d_in, const int* in_sizes, int n_in,
                              void* d_out, int out_size)
{
    const float* x  = (const float*)d_in[0];
    const float* Wq = (const float*)d_in[1];
    const float* bq = (const float*)d_in[2];
    const float* Wk = (const float*)d_in[3];
    const float* bk = (const float*)d_in[4];
    const float* Wv = (const float*)d_in[5];
    const float* bv = (const float*)d_in[6];
    float* out = (float*)d_out;

    __half *xh, *xl, *wt16, *qh, *ql, *k16, *vt16, *ph, *pl;
    float* s;
    cudaGetSymbolAddress((void**)&xh,   g_xh);
    cudaGetSymbolAddress((void**)&xl,   g_xl);
    cudaGetSymbolAddress((void**)&wt16, g_wt16);
    cudaGetSymbolAddress((void**)&qh,   g_qh);
    cudaGetSymbolAddress((void**)&ql,   g_ql);
    cudaGetSymbolAddress((void**)&k16,  g_k16);
    cudaGetSymbolAddress((void**)&vt16, g_vt16);
    cudaGetSymbolAddress((void**)&s,    g_s);
    cudaGetSymbolAddress((void**)&ph,   g_ph);
    cudaGetSymbolAddress((void**)&pl,   g_pl);

    cudaFuncSetAttribute(gemm_fp16x2<0>, cudaFuncAttributeMaxDynamicSharedMemorySize, SMEM_TOTAL);
    cudaFuncSetAttribute(gemm_fp16x2<1>, cudaFuncAttributeMaxDynamicSharedMemorySize, SMEM_TOTAL);

    // prep: split x (fp16 hi/lo), transpose W -> fp16
    split_kernel<<<4096, 256>>>(x, xh, xl, (long long)BN_ROWS * DIM / 2);
    {
        dim3 g(DIM / 32, DIM / 32), b(32, 8);
        wtrans_kernel<<<g, b>>>(Wq, wt16);
        wtrans_kernel<<<g, b>>>(Wk, wt16 + (size_t)DIM * DIM);
        wtrans_kernel<<<g, b>>>(Wv, wt16 + 2 * (size_t)DIM * DIM);
    }

    const dim3 blk(256);
    const long long sQK = (long long)SEQ * DIM;
    const long long sSS = (long long)SEQ * SEQ;

    // fused QKV projections (fp16 x2: x split, W single)
    {
        dim3 g(DIM / TNt, BN_ROWS / TMt, 3);   // (8, 128, 3)
        gemm_fp16x2<0><<<g, blk, SMEM_TOTAL>>>(xh, xl, DIM, wt16, DIM,
                                               bq, bk, bv, nullptr,
                                               qh, ql, k16, vt16,
                                               DIM, DIM, 0, (long long)DIM * DIM, 0);
    }
    // scores = Q @ K^T   (Q split, K single)
    {
        dim3 g(SEQ / TNt, SEQ / TMt, BATCH);   // (16, 16, 8)
        gemm_fp16x2<1><<<g, blk, SMEM_TOTAL>>>(qh, ql, DIM, k16, DIM,
                                               nullptr, nullptr, nullptr, s,
                                               nullptr, nullptr, nullptr, nullptr,
                                               SEQ, DIM, sQK, sQK, sSS);
    }
    // softmax + fp16 split
    softmax_split_kernel<<<BATCH * SEQ, 256>>>(s, ph, pl);
    // out = P @ V   (P split, V^T single; K=SEQ)
    {
        dim3 g(DIM / TNt, SEQ / TMt, BATCH);   // (8, 16, 8)
        gemm_fp16x2<1><<<g, blk, SMEM_TOTAL>>>(ph, pl, SEQ, vt16, SEQ,
                                               nullptr, nullptr, nullptr, out,
                                               nullptr, nullptr, nullptr, nullptr,
                                               DIM, SEQ, sSS, (long long)DIM * SEQ, sQK);
    }
}

// round 8
// speedup vs baseline: 2.1825x; 1.5459x over previous
#include <cuda_runtime.h>
#include <cuda_fp16.h>
#include <cstdint>
#include <math.h>

#define BATCH 8
#define SEQ   2048
#define DIM   1024
#define BN_ROWS (BATCH * SEQ)     // 16384

// ---------------- tile config ----------------
#define TMt 128
#define TNt 128
#define TKt 64                     // fp16 elems per k-chunk (128B rows, SW128)

static constexpr int OFF_A = 0;
static constexpr int OFF_B = 16384;
static constexpr int STAGE_BYTES = 32768;
static constexpr int NSTAGE = 3;
static constexpr int SMEM_TOTAL = NSTAGE * STAGE_BYTES;  // 98304

// ---------------- scratch (__device__ globals; no allocs allowed) --------------
__device__ __half g_x16[(long long)BN_ROWS * DIM];       // x fp16
__device__ __half g_wt16[3u * DIM * DIM];                // W^T fp16 (q,k,v)
__device__ __half g_q16[(long long)BN_ROWS * DIM];       // Q fp16
__device__ __half g_k16[(long long)BN_ROWS * DIM];       // K fp16
__device__ __half g_vt16[(long long)BATCH * DIM * SEQ];  // V^T fp16 [b][dim][seq]
__device__ float  g_s [(long long)BATCH * SEQ * SEQ];    // fp32 scores
__device__ __half g_p16[(long long)BATCH * SEQ * SEQ];   // P fp16

// ---------------- PTX helpers ----------------
__device__ __forceinline__ uint32_t smem_u32(const void* p) {
    uint32_t a;
    asm("{ .reg .u64 t; cvta.to.shared.u64 t, %1; cvt.u32.u64 %0, t; }" : "=r"(a) : "l"(p));
    return a;
}
__device__ __forceinline__ void cp16(uint32_t saddr, const void* g) {
    asm volatile("cp.async.cg.shared.global [%0], [%1], 16;" :: "r"(saddr), "l"(g));
}
#define CP_COMMIT() asm volatile("cp.async.commit_group;" ::: "memory")
#define CP_WAIT1()  asm volatile("cp.async.wait_group 1;" ::: "memory")
#define CP_WAIT0()  asm volatile("cp.async.wait_group 0;" ::: "memory")

__device__ __forceinline__ void ldsm_x4(uint32_t (&r)[4], uint32_t addr) {
    asm volatile("ldmatrix.sync.aligned.m8n8.x4.shared.b16 {%0,%1,%2,%3}, [%4];"
        : "=r"(r[0]), "=r"(r[1]), "=r"(r[2]), "=r"(r[3]) : "r"(addr));
}
__device__ __forceinline__ void mma_f16(float (&d)[4], const uint32_t (&a)[4],
                                        uint32_t b0, uint32_t b1) {
    asm volatile("mma.sync.aligned.m16n8k16.row.col.f32.f16.f16.f32 "
        "{%0,%1,%2,%3}, {%4,%5,%6,%7}, {%8,%9}, {%0,%1,%2,%3};"
        : "+f"(d[0]), "+f"(d[1]), "+f"(d[2]), "+f"(d[3])
        : "r"(a[0]), "r"(a[1]), "r"(a[2]), "r"(a[3]), "r"(b0), "r"(b1));
}
__device__ __forceinline__ uint32_t sw128(uint32_t off) {
    return off ^ (((off >> 7) & 7) << 4);
}

// ==================== fp16 single-product GEMM ====================
// C[M,N] = A[M,K] @ B[N,K]^T, fp32 accumulate, both operands fp16.
// MODE 0: fused QKV. z: 0 -> Q (+biasQ, row-major fp16)
//                       1 -> K (+biasK, row-major fp16)
//                       2 -> V (+biasV, transposed per batch fp16)
// MODE 1: fp32 out (scores / final), batch via z.
template <int MODE>
__global__ __launch_bounds__(256, 1)
void gemm_fp16(const __half* __restrict__ A, int lda,
               const __half* __restrict__ B, int ldb,
               const float* __restrict__ biasQ, const float* __restrict__ biasK, const float* __restrict__ biasV,
               float* __restrict__ Fo,
               __half* __restrict__ Oq, __half* __restrict__ Ok, __half* __restrict__ Ov,
               int ldo, int K, long long sA, long long sB, long long sO)
{
    extern __shared__ __align__(1024) char smem[];
    const uint32_t smb = smem_u32(smem);
    const int tid  = threadIdx.x;
    const int lane = tid & 31;
    const int wid  = tid >> 5;
    const int wm   = wid & 3;          // 4 warps along M
    const int wn   = wid >> 2;         // 2 warps along N
    const int z = blockIdx.z;
    const int rowBase = blockIdx.y * TMt;
    const int colBase = blockIdx.x * TNt;

    const __half* Ap = A + sA * z + (long long)rowBase * lda;
    const __half* Bp = B + sB * z + (long long)colBase * ldb;

    auto load_stage = [&](int st, int kt) {
        const int k0 = kt * TKt;
        const uint32_t sb = smb + st * STAGE_BYTES;
#pragma unroll
        for (int i = 0; i < 4; i++) {
            const int c  = tid + i * 256;      // 0..1023
            const int r  = c >> 3;
            const int cc = c & 7;
            const uint32_t sw = sw128((uint32_t)(r * 128 + cc * 16));
            cp16(sb + OFF_A + sw, Ap + (long long)r * lda + k0 + cc * 8);
            cp16(sb + OFF_B + sw, Bp + (long long)r * ldb + k0 + cc * 8);
        }
        CP_COMMIT();
    };

    float acc[2][8][4];
#pragma unroll
    for (int a = 0; a < 2; a++)
#pragma unroll
        for (int b = 0; b < 8; b++)
#pragma unroll
            for (int c = 0; c < 4; c++) acc[a][b][c] = 0.f;

    const int nk = K / TKt;
    load_stage(0, 0);
    load_stage(1, 1);

    for (int t = 0; t < nk; t++) {
        if (t + 1 < nk) { CP_WAIT1(); } else { CP_WAIT0(); }
        __syncthreads();
        if (t + 2 < nk) load_stage((t + 2) % NSTAGE, t + 2);

        const uint32_t sb = smb + (t % NSTAGE) * STAGE_BYTES;
#pragma unroll
        for (int kk = 0; kk < TKt; kk += 16) {
            uint32_t af[2][4], bf[4][4];
#pragma unroll
            for (int mt = 0; mt < 2; mt++) {
                const int r = wm * 32 + mt * 16 + (lane & 15);
                const uint32_t sw = sw128((uint32_t)(r * 128 + kk * 2 + ((lane >> 4) << 4)));
                ldsm_x4(af[mt], sb + OFF_A + sw);
            }
#pragma unroll
            for (int np = 0; np < 4; np++) {
                const int r = wn * 64 + np * 16 + (lane & 7) + ((lane >> 4) << 3);
                const uint32_t sw = sw128((uint32_t)(r * 128 + kk * 2 + (((lane >> 3) & 1) << 4)));
                ldsm_x4(bf[np], sb + OFF_B + sw);
            }
#pragma unroll
            for (int mt = 0; mt < 2; mt++)
#pragma unroll
                for (int np = 0; np < 4; np++) {
                    mma_f16(acc[mt][np * 2 + 0], af[mt], bf[np][0], bf[np][1]);
                    mma_f16(acc[mt][np * 2 + 1], af[mt], bf[np][2], bf[np][3]);
                }
        }
    }

    // ---------------- epilogue ----------------
    const int mB = wm * 32;
    const int nB = wn * 64;

    if (MODE == 1) {
#pragma unroll
        for (int mt = 0; mt < 2; mt++)
#pragma unroll
            for (int nt = 0; nt < 8; nt++)
#pragma unroll
                for (int h = 0; h < 2; h++) {
                    const int m = rowBase + mB + mt * 16 + (lane >> 2) + h * 8;
                    const int n = colBase + nB + nt * 8 + ((lane & 3) << 1);
                    float2 fv;
                    fv.x = acc[mt][nt][h * 2 + 0];
                    fv.y = acc[mt][nt][h * 2 + 1];
                    *(float2*)(Fo + sO * z + (long long)m * ldo + n) = fv;
                }
    } else if (z != 2) {
        // Q or K: fp16 row-major (+bias)
        const float* bias = (z == 0) ? biasQ : biasK;
        __half* O = (z == 0) ? Oq : Ok;
#pragma unroll
        for (int mt = 0; mt < 2; mt++)
#pragma unroll
            for (int nt = 0; nt < 8; nt++)
#pragma unroll
                for (int h = 0; h < 2; h++) {
                    const int m = rowBase + mB + mt * 16 + (lane >> 2) + h * 8;
                    const int n = colBase + nB + nt * 8 + ((lane & 3) << 1);
                    __half2 hv;
                    hv.x = __float2half_rn(acc[mt][nt][h * 2 + 0] + __ldg(&bias[n]));
                    hv.y = __float2half_rn(acc[mt][nt][h * 2 + 1] + __ldg(&bias[n + 1]));
                    *(__half2*)(O + (long long)m * DIM + n) = hv;
                }
    } else {
        // V: fp16, transposed per batch via smem bounce
        __half* Th = (__half*)smem;     // [128 n][136 m]
        __syncthreads();
#pragma unroll
        for (int mt = 0; mt < 2; mt++)
#pragma unroll
            for (int nt = 0; nt < 8; nt++)
#pragma unroll
                for (int h = 0; h < 2; h++) {
                    const int ml = mB + mt * 16 + (lane >> 2) + h * 8;
                    const int nl = nB + nt * 8 + ((lane & 3) << 1);
#pragma unroll
                    for (int j = 0; j < 2; j++) {
                        float v = acc[mt][nt][h * 2 + j] + __ldg(&biasV[colBase + nl + j]);
                        Th[(nl + j) * 136 + ml] = __float2half_rn(v);
                    }
                }
        __syncthreads();
        const int b   = rowBase >> 11;
        const int pos = rowBase & (SEQ - 1);
        const long long bb = (long long)b * DIM * SEQ + pos;
        for (int c = tid; c < 128 * 16; c += 256) {
            const int nr = c >> 4;
            const int cc = c & 15;
            const long long go = bb + (long long)(colBase + nr) * SEQ + cc * 8;
            *(uint4*)(Ov + go) = *(uint4*)(Th + nr * 136 + cc * 8);
        }
    }
}

// ---------------- prep kernels ----------------
// fp32 -> fp16 convert
__global__ void cvt_kernel(const float* __restrict__ src, __half* __restrict__ dst, long long n2)
{
    const long long stride = (long long)gridDim.x * blockDim.x;
    for (long long i = (long long)blockIdx.x * blockDim.x + threadIdx.x; i < n2; i += stride) {
        const float2 a = ((const float2*)src)[i];
        __half2 h;
        h.x = __float2half_rn(a.x);
        h.y = __float2half_rn(a.y);
        ((__half2*)dst)[i] = h;
    }
}

// transpose [DIM,DIM] fp32 W -> fp16 Wt (Wt[n][k] = W[k][n])
__global__ void wtrans_kernel(const float* __restrict__ W, __half* __restrict__ T16)
{
    __shared__ float t[32][33];
    const int x = blockIdx.x * 32 + threadIdx.x;
    const int y0 = blockIdx.y * 32;
#pragma unroll
    for (int i = 0; i < 32; i += 8)
        t[threadIdx.y + i][threadIdx.x] = W[(long long)(y0 + threadIdx.y + i) * DIM + x];
    __syncthreads();
#pragma unroll
    for (int i = 0; i < 32; i += 8) {
        const float val = t[threadIdx.x][threadIdx.y + i];
        const int n = blockIdx.x * 32 + threadIdx.y + i;
        const int k = y0 + threadIdx.x;
        T16[(long long)n * DIM + k] = __float2half_rn(val);
    }
}

// row softmax (with 1/sqrt(D) scale) -> fp16 probs
__global__ void softmax_kernel(const float* __restrict__ S, __half* __restrict__ P16)
{
    const long long row = blockIdx.x;
    const float* p = S + row * (long long)SEQ;
    const int t = threadIdx.x;

    __shared__ float sh[32];
    const float scale = 0.03125f;

    float v[8];
    float mx = -INFINITY;
#pragma unroll
    for (int i = 0; i < 8; i++) {
        v[i] = p[t + i * 256] * scale;
        mx = fmaxf(mx, v[i]);
    }
#pragma unroll
    for (int o = 16; o; o >>= 1) mx = fmaxf(mx, __shfl_xor_sync(0xffffffffu, mx, o));
    if ((t & 31) == 0) sh[t >> 5] = mx;
    __syncthreads();
    if (t == 0) {
        float m = sh[0];
#pragma unroll
        for (int w = 1; w < 8; w++) m = fmaxf(m, sh[w]);
        sh[0] = m;
    }
    __syncthreads();
    mx = sh[0];

    float sum = 0.f;
#pragma unroll
    for (int i = 0; i < 8; i++) {
        v[i] = __expf(v[i] - mx);
        sum += v[i];
    }
#pragma unroll
    for (int o = 16; o; o >>= 1) sum += __shfl_xor_sync(0xffffffffu, sum, o);
    __syncthreads();
    if ((t & 31) == 0) sh[t >> 5] = sum;
    __syncthreads();
    if (t == 0) {
        float s = 0.f;
#pragma unroll
        for (int w = 0; w < 8; w++) s += sh[w];
        sh[0] = s;
    }
    __syncthreads();
    const float inv = 1.0f / sh[0];

#pragma unroll
    for (int i = 0; i < 8; i++)
        P16[row * (long long)SEQ + t + i * 256] = __float2half_rn(v[i] * inv);
}

// ---------------- launch ----------------
extern "C" void kernel_launch(void* const* d_in, const int* in_sizes, int n_in,
                              void* d_out, int out_size)
{
    const float* x  = (const float*)d_in[0];
    const float* Wq = (const float*)d_in[1];
    const float* bq = (const float*)d_in[2];
    const float* Wk = (const float*)d_in[3];
    const float* bk = (const float*)d_in[4];
    const float* Wv = (const float*)d_in[5];
    const float* bv = (const float*)d_in[6];
    float* out = (float*)d_out;

    __half *x16, *wt16, *q16, *k16, *vt16, *p16;
    float* s;
    cudaGetSymbolAddress((void**)&x16,  g_x16);
    cudaGetSymbolAddress((void**)&wt16, g_wt16);
    cudaGetSymbolAddress((void**)&q16,  g_q16);
    cudaGetSymbolAddress((void**)&k16,  g_k16);
    cudaGetSymbolAddress((void**)&vt16, g_vt16);
    cudaGetSymbolAddress((void**)&s,    g_s);
    cudaGetSymbolAddress((void**)&p16,  g_p16);

    cudaFuncSetAttribute(gemm_fp16<0>, cudaFuncAttributeMaxDynamicSharedMemorySize, SMEM_TOTAL);
    cudaFuncSetAttribute(gemm_fp16<1>, cudaFuncAttributeMaxDynamicSharedMemorySize, SMEM_TOTAL);

    // prep: convert x -> fp16, transpose W -> fp16
    cvt_kernel<<<4096, 256>>>(x, x16, (long long)BN_ROWS * DIM / 2);
    {
        dim3 g(DIM / 32, DIM / 32), b(32, 8);
        wtrans_kernel<<<g, b>>>(Wq, wt16);
        wtrans_kernel<<<g, b>>>(Wk, wt16 + (size_t)DIM * DIM);
        wtrans_kernel<<<g, b>>>(Wv, wt16 + 2 * (size_t)DIM * DIM);
    }

    const dim3 blk(256);
    const long long sQK = (long long)SEQ * DIM;
    const long long sSS = (long long)SEQ * SEQ;

    // fused QKV projections
    {
        dim3 g(DIM / TNt, BN_ROWS / TMt, 3);   // (8, 128, 3)
        gemm_fp16<0><<<g, blk, SMEM_TOTAL>>>(x16, DIM, wt16, DIM,
                                             bq, bk, bv, nullptr,
                                             q16, k16, vt16,
                                             DIM, DIM, 0, (long long)DIM * DIM, 0);
    }
    // scores = Q @ K^T
    {
        dim3 g(SEQ / TNt, SEQ / TMt, BATCH);   // (16, 16, 8)
        gemm_fp16<1><<<g, blk, SMEM_TOTAL>>>(q16, DIM, k16, DIM,
                                             nullptr, nullptr, nullptr, s,
                                             nullptr, nullptr, nullptr,
                                             SEQ, DIM, sQK, sQK, sSS);
    }
    // softmax -> fp16 P
    softmax_kernel<<<BATCH * SEQ, 256>>>(s, p16);
    // out = P @ V   (V^T, K=SEQ)
    {
        dim3 g(DIM / TNt, SEQ / TMt, BATCH);   // (8, 16, 8)
        gemm_fp16<1><<<g, blk, SMEM_TOTAL>>>(p16, SEQ, vt16, SEQ,
                                             nullptr, nullptr, nullptr, out,
                                             nullptr, nullptr, nullptr,
                                             DIM, SEQ, sSS, (long long)DIM * SEQ, sQK);
    }
}

// round 9
// speedup vs baseline: 2.7114x; 1.2423x over previous
#include <cuda_runtime.h>
#include <cuda_fp16.h>
#include <cstdint>
#include <math.h>

#define BATCH 8
#define SEQ   2048
#define DIM   1024
#define BN_ROWS (BATCH * SEQ)     // 16384

// ---------------- tile config ----------------
#define TMt 128
#define TNt 128
#define TKt 64                     // fp16 elems per k-chunk (128B rows, SW128)

static constexpr int OFF_A = 0;
static constexpr int OFF_B = 16384;
static constexpr int STAGE_BYTES = 32768;
static constexpr int NSTAGE = 3;
static constexpr int SMEM_TOTAL = NSTAGE * STAGE_BYTES;  // 98304 -> 2 CTAs/SM (192KB of 228KB)

// ---------------- scratch (__device__ globals; no allocs allowed) --------------
__device__ __half g_x16[(long long)BN_ROWS * DIM];       // x fp16
__device__ __half g_wt16[3u * DIM * DIM];                // W^T fp16 (q,k,v)
__device__ __half g_q16[(long long)BN_ROWS * DIM];       // Q fp16
__device__ __half g_k16[(long long)BN_ROWS * DIM];       // K fp16
__device__ __half g_vt16[(long long)BATCH * DIM * SEQ];  // V^T fp16 [b][dim][seq]
__device__ float  g_s [(long long)BATCH * SEQ * SEQ];    // fp32 scores
__device__ __half g_p16[(long long)BATCH * SEQ * SEQ];   // P fp16

// ---------------- PTX helpers ----------------
__device__ __forceinline__ uint32_t smem_u32(const void* p) {
    uint32_t a;
    asm("{ .reg .u64 t; cvta.to.shared.u64 t, %1; cvt.u32.u64 %0, t; }" : "=r"(a) : "l"(p));
    return a;
}
__device__ __forceinline__ void cp16(uint32_t saddr, const void* g) {
    asm volatile("cp.async.cg.shared.global [%0], [%1], 16;" :: "r"(saddr), "l"(g));
}
#define CP_COMMIT() asm volatile("cp.async.commit_group;" ::: "memory")
#define CP_WAIT1()  asm volatile("cp.async.wait_group 1;" ::: "memory")
#define CP_WAIT0()  asm volatile("cp.async.wait_group 0;" ::: "memory")

__device__ __forceinline__ void ldsm_x4(uint32_t (&r)[4], uint32_t addr) {
    asm volatile("ldmatrix.sync.aligned.m8n8.x4.shared.b16 {%0,%1,%2,%3}, [%4];"
        : "=r"(r[0]), "=r"(r[1]), "=r"(r[2]), "=r"(r[3]) : "r"(addr));
}
__device__ __forceinline__ void mma_f16(float (&d)[4], const uint32_t (&a)[4],
                                        uint32_t b0, uint32_t b1) {
    asm volatile("mma.sync.aligned.m16n8k16.row.col.f32.f16.f16.f32 "
        "{%0,%1,%2,%3}, {%4,%5,%6,%7}, {%8,%9}, {%0,%1,%2,%3};"
        : "+f"(d[0]), "+f"(d[1]), "+f"(d[2]), "+f"(d[3])
        : "r"(a[0]), "r"(a[1]), "r"(a[2]), "r"(a[3]), "r"(b0), "r"(b1));
}
__device__ __forceinline__ uint32_t sw128(uint32_t off) {
    return off ^ (((off >> 7) & 7) << 4);
}

// ==================== fp16 single-product GEMM ====================
// C[M,N] = A[M,K] @ B[N,K]^T, fp32 accumulate, both operands fp16.
// MODE 0: fused QKV. z: 0 -> Q (+biasQ, row-major fp16)
//                       1 -> K (+biasK, row-major fp16)
//                       2 -> V (+biasV, transposed per batch fp16)
// MODE 1: fp32 out (scores / final), batch via z.
template <int MODE>
__global__ __launch_bounds__(256, 2)
void gemm_fp16(const __half* __restrict__ A, int lda,
               const __half* __restrict__ B, int ldb,
               const float* __restrict__ biasQ, const float* __restrict__ biasK, const float* __restrict__ biasV,
               float* __restrict__ Fo,
               __half* __restrict__ Oq, __half* __restrict__ Ok, __half* __restrict__ Ov,
               int ldo, int K, long long sA, long long sB, long long sO)
{
    extern __shared__ __align__(1024) char smem[];
    const uint32_t smb = smem_u32(smem);
    const int tid  = threadIdx.x;
    const int lane = tid & 31;
    const int wid  = tid >> 5;
    const int wm   = wid & 3;          // 4 warps along M
    const int wn   = wid >> 2;         // 2 warps along N
    const int z = blockIdx.z;
    const int rowBase = blockIdx.y * TMt;
    const int colBase = blockIdx.x * TNt;

    const __half* Ap = A + sA * z + (long long)rowBase * lda;
    const __half* Bp = B + sB * z + (long long)colBase * ldb;

    auto load_stage = [&](int st, int kt) {
        const int k0 = kt * TKt;
        const uint32_t sb = smb + st * STAGE_BYTES;
#pragma unroll
        for (int i = 0; i < 4; i++) {
            const int c  = tid + i * 256;      // 0..1023
            const int r  = c >> 3;
            const int cc = c & 7;
            const uint32_t sw = sw128((uint32_t)(r * 128 + cc * 16));
            cp16(sb + OFF_A + sw, Ap + (long long)r * lda + k0 + cc * 8);
            cp16(sb + OFF_B + sw, Bp + (long long)r * ldb + k0 + cc * 8);
        }
        CP_COMMIT();
    };

    float acc[2][8][4];
#pragma unroll
    for (int a = 0; a < 2; a++)
#pragma unroll
        for (int b = 0; b < 8; b++)
#pragma unroll
            for (int c = 0; c < 4; c++) acc[a][b][c] = 0.f;

    const int nk = K / TKt;
    load_stage(0, 0);
    load_stage(1, 1);

    for (int t = 0; t < nk; t++) {
        if (t + 1 < nk) { CP_WAIT1(); } else { CP_WAIT0(); }
        __syncthreads();
        if (t + 2 < nk) load_stage((t + 2) % NSTAGE, t + 2);

        const uint32_t sb = smb + (t % NSTAGE) * STAGE_BYTES;
#pragma unroll
        for (int kk = 0; kk < TKt; kk += 16) {
            uint32_t af[2][4], bf[4][4];
#pragma unroll
            for (int mt = 0; mt < 2; mt++) {
                const int r = wm * 32 + mt * 16 + (lane & 15);
                const uint32_t sw = sw128((uint32_t)(r * 128 + kk * 2 + ((lane >> 4) << 4)));
                ldsm_x4(af[mt], sb + OFF_A + sw);
            }
#pragma unroll
            for (int np = 0; np < 4; np++) {
                const int r = wn * 64 + np * 16 + (lane & 7) + ((lane >> 4) << 3);
                const uint32_t sw = sw128((uint32_t)(r * 128 + kk * 2 + (((lane >> 3) & 1) << 4)));
                ldsm_x4(bf[np], sb + OFF_B + sw);
            }
#pragma unroll
            for (int mt = 0; mt < 2; mt++)
#pragma unroll
                for (int np = 0; np < 4; np++) {
                    mma_f16(acc[mt][np * 2 + 0], af[mt], bf[np][0], bf[np][1]);
                    mma_f16(acc[mt][np * 2 + 1], af[mt], bf[np][2], bf[np][3]);
                }
        }
    }

    // ---------------- epilogue ----------------
    const int mB = wm * 32;
    const int nB = wn * 64;

    if (MODE == 1) {
#pragma unroll
        for (int mt = 0; mt < 2; mt++)
#pragma unroll
            for (int nt = 0; nt < 8; nt++)
#pragma unroll
                for (int h = 0; h < 2; h++) {
                    const int m = rowBase + mB + mt * 16 + (lane >> 2) + h * 8;
                    const int n = colBase + nB + nt * 8 + ((lane & 3) << 1);
                    float2 fv;
                    fv.x = acc[mt][nt][h * 2 + 0];
                    fv.y = acc[mt][nt][h * 2 + 1];
                    *(float2*)(Fo + sO * z + (long long)m * ldo + n) = fv;
                }
    } else if (z != 2) {
        // Q or K: fp16 row-major (+bias)
        const float* bias = (z == 0) ? biasQ : biasK;
        __half* O = (z == 0) ? Oq : Ok;
#pragma unroll
        for (int mt = 0; mt < 2; mt++)
#pragma unroll
            for (int nt = 0; nt < 8; nt++)
#pragma unroll
                for (int h = 0; h < 2; h++) {
                    const int m = rowBase + mB + mt * 16 + (lane >> 2) + h * 8;
                    const int n = colBase + nB + nt * 8 + ((lane & 3) << 1);
                    __half2 hv;
                    hv.x = __float2half_rn(acc[mt][nt][h * 2 + 0] + __ldg(&bias[n]));
                    hv.y = __float2half_rn(acc[mt][nt][h * 2 + 1] + __ldg(&bias[n + 1]));
                    *(__half2*)(O + (long long)m * DIM + n) = hv;
                }
    } else {
        // V: fp16, transposed per batch via smem bounce
        __half* Th = (__half*)smem;     // [128 n][136 m]
        __syncthreads();
#pragma unroll
        for (int mt = 0; mt < 2; mt++)
#pragma unroll
            for (int nt = 0; nt < 8; nt++)
#pragma unroll
                for (int h = 0; h < 2; h++) {
                    const int ml = mB + mt * 16 + (lane >> 2) + h * 8;
                    const int nl = nB + nt * 8 + ((lane & 3) << 1);
#pragma unroll
                    for (int j = 0; j < 2; j++) {
                        float v = acc[mt][nt][h * 2 + j] + __ldg(&biasV[colBase + nl + j]);
                        Th[(nl + j) * 136 + ml] = __float2half_rn(v);
                    }
                }
        __syncthreads();
        const int b   = rowBase >> 11;
        const int pos = rowBase & (SEQ - 1);
        const long long bb = (long long)b * DIM * SEQ + pos;
        for (int c = tid; c < 128 * 16; c += 256) {
            const int nr = c >> 4;
            const int cc = c & 15;
            const long long go = bb + (long long)(colBase + nr) * SEQ + cc * 8;
            *(uint4*)(Ov + go) = *(uint4*)(Th + nr * 136 + cc * 8);
        }
    }
}

// ---------------- prep kernels ----------------
// fp32 -> fp16 convert
__global__ void cvt_kernel(const float* __restrict__ src, __half* __restrict__ dst, long long n2)
{
    const long long stride = (long long)gridDim.x * blockDim.x;
    for (long long i = (long long)blockIdx.x * blockDim.x + threadIdx.x; i < n2; i += stride) {
        const float2 a = ((const float2*)src)[i];
        __half2 h;
        h.x = __float2half_rn(a.x);
        h.y = __float2half_rn(a.y);
        ((__half2*)dst)[i] = h;
    }
}

// transpose [DIM,DIM] fp32 W -> fp16 Wt (Wt[n][k] = W[k][n])
__global__ void wtrans_kernel(const float* __restrict__ W, __half* __restrict__ T16)
{
    __shared__ float t[32][33];
    const int x = blockIdx.x * 32 + threadIdx.x;
    const int y0 = blockIdx.y * 32;
#pragma unroll
    for (int i = 0; i < 32; i += 8)
        t[threadIdx.y + i][threadIdx.x] = W[(long long)(y0 + threadIdx.y + i) * DIM + x];
    __syncthreads();
#pragma unroll
    for (int i = 0; i < 32; i += 8) {
        const float val = t[threadIdx.x][threadIdx.y + i];
        const int n = blockIdx.x * 32 + threadIdx.y + i;
        const int k = y0 + threadIdx.x;
        T16[(long long)n * DIM + k] = __float2half_rn(val);
    }
}

// row softmax (with 1/sqrt(D) scale) -> fp16 probs
__global__ void softmax_kernel(const float* __restrict__ S, __half* __restrict__ P16)
{
    const long long row = blockIdx.x;
    const float* p = S + row * (long long)SEQ;
    const int t = threadIdx.x;

    __shared__ float sh[32];
    const float scale = 0.03125f;

    float v[8];
    float mx = -INFINITY;
#pragma unroll
    for (int i = 0; i < 8; i++) {
        v[i] = p[t + i * 256] * scale;
        mx = fmaxf(mx, v[i]);
    }
#pragma unroll
    for (int o = 16; o; o >>= 1) mx = fmaxf(mx, __shfl_xor_sync(0xffffffffu, mx, o));
    if ((t & 31) == 0) sh[t >> 5] = mx;
    __syncthreads();
    if (t == 0) {
        float m = sh[0];
#pragma unroll
        for (int w = 1; w < 8; w++) m = fmaxf(m, sh[w]);
        sh[0] = m;
    }
    __syncthreads();
    mx = sh[0];

    float sum = 0.f;
#pragma unroll
    for (int i = 0; i < 8; i++) {
        v[i] = __expf(v[i] - mx);
        sum += v[i];
    }
#pragma unroll
    for (int o = 16; o; o >>= 1) sum += __shfl_xor_sync(0xffffffffu, sum, o);
    __syncthreads();
    if ((t & 31) == 0) sh[t >> 5] = sum;
    __syncthreads();
    if (t == 0) {
        float s = 0.f;
#pragma unroll
        for (int w = 0; w < 8; w++) s += sh[w];
        sh[0] = s;
    }
    __syncthreads();
    const float inv = 1.0f / sh[0];

#pragma unroll
    for (int i = 0; i < 8; i++)
        P16[row * (long long)SEQ + t + i * 256] = __float2half_rn(v[i] * inv);
}

// ---------------- launch ----------------
extern "C" void kernel_launch(void* const* d_in, const int* in_sizes, int n_in,
                              void* d_out, int out_size)
{
    const float* x  = (const float*)d_in[0];
    const float* Wq = (const float*)d_in[1];
    const float* bq = (const float*)d_in[2];
    const float* Wk = (const float*)d_in[3];
    const float* bk = (const float*)d_in[4];
    const float* Wv = (const float*)d_in[5];
    const float* bv = (const float*)d_in[6];
    float* out = (float*)d_out;

    __half *x16, *wt16, *q16, *k16, *vt16, *p16;
    float* s;
    cudaGetSymbolAddress((void**)&x16,  g_x16);
    cudaGetSymbolAddress((void**)&wt16, g_wt16);
    cudaGetSymbolAddress((void**)&q16,  g_q16);
    cudaGetSymbolAddress((void**)&k16,  g_k16);
    cudaGetSymbolAddress((void**)&vt16, g_vt16);
    cudaGetSymbolAddress((void**)&s,    g_s);
    cudaGetSymbolAddress((void**)&p16,  g_p16);

    cudaFuncSetAttribute(gemm_fp16<0>, cudaFuncAttributeMaxDynamicSharedMemorySize, SMEM_TOTAL);
    cudaFuncSetAttribute(gemm_fp16<1>, cudaFuncAttributeMaxDynamicSharedMemorySize, SMEM_TOTAL);

    // prep: convert x -> fp16, transpose W -> fp16
    cvt_kernel<<<4096, 256>>>(x, x16, (long long)BN_ROWS * DIM / 2);
    {
        dim3 g(DIM / 32, DIM / 32), b(32, 8);
        wtrans_kernel<<<g, b>>>(Wq, wt16);
        wtrans_kernel<<<g, b>>>(Wk, wt16 + (size_t)DIM * DIM);
        wtrans_kernel<<<g, b>>>(Wv, wt16 + 2 * (size_t)DIM * DIM);
    }

    const dim3 blk(256);
    const long long sQK = (long long)SEQ * DIM;
    const long long sSS = (long long)SEQ * SEQ;

    // fused QKV projections
    {
        dim3 g(DIM / TNt, BN_ROWS / TMt, 3);   // (8, 128, 3)
        gemm_fp16<0><<<g, blk, SMEM_TOTAL>>>(x16, DIM, wt16, DIM,
                                             bq, bk, bv, nullptr,
                                             q16, k16, vt16,
                                             DIM, DIM, 0, (long long)DIM * DIM, 0);
    }
    // scores = Q @ K^T
    {
        dim3 g(SEQ / TNt, SEQ / TMt, BATCH);   // (16, 16, 8)
        gemm_fp16<1><<<g, blk, SMEM_TOTAL>>>(q16, DIM, k16, DIM,
                                             nullptr, nullptr, nullptr, s,
                                             nullptr, nullptr, nullptr,
                                             SEQ, DIM, sQK, sQK, sSS);
    }
    // softmax -> fp16 P
    softmax_kernel<<<BATCH * SEQ, 256>>>(s, p16);
    // out = P @ V   (V^T, K=SEQ)
    {
        dim3 g(DIM / TNt, SEQ / TMt, BATCH);   // (8, 16, 8)
        gemm_fp16<1><<<g, blk, SMEM_TOTAL>>>(p16, SEQ, vt16, SEQ,
                                             nullptr, nullptr, nullptr, out,
                                             nullptr, nullptr, nullptr,
                                             DIM, SEQ, sSS, (long long)DIM * SEQ, sQK);
    }
}

// round 10
// speedup vs baseline: 2.7578x; 1.0171x over previous
#include <cuda_runtime.h>
#include <cuda_fp16.h>
#include <cstdint>
#include <math.h>

#define BATCH 8
#define SEQ   2048
#define DIM   1024
#define BN_ROWS (BATCH * SEQ)     // 16384

// ---------------- tile config ----------------
#define TMt 128
#define TNt 128
#define TKt 64                     // fp16 elems per k-chunk (128B rows, SW128)

static constexpr int OFF_A = 0;
static constexpr int OFF_B = 16384;
static constexpr int STAGE_BYTES = 32768;
static constexpr int NSTAGE = 3;
static constexpr int SMEM_TOTAL = NSTAGE * STAGE_BYTES;  // 98304 -> 2 CTAs/SM

// ---------------- scratch (__device__ globals; no allocs allowed) --------------
__device__ __half g_x16[(long long)BN_ROWS * DIM];       // x fp16
__device__ __half g_wt16[3u * DIM * DIM];                // W^T fp16 (q,k,v)
__device__ __half g_q16[(long long)BN_ROWS * DIM];       // Q fp16
__device__ __half g_k16[(long long)BN_ROWS * DIM];       // K fp16
__device__ __half g_vt16[(long long)BATCH * DIM * SEQ];  // V^T fp16 [b][dim][seq]
__device__ __half g_s16[(long long)BATCH * SEQ * SEQ];   // fp16 scores
__device__ __half g_p16[(long long)BATCH * SEQ * SEQ];   // P fp16

// ---------------- PTX helpers ----------------
__device__ __forceinline__ uint32_t smem_u32(const void* p) {
    uint32_t a;
    asm("{ .reg .u64 t; cvta.to.shared.u64 t, %1; cvt.u32.u64 %0, t; }" : "=r"(a) : "l"(p));
    return a;
}
__device__ __forceinline__ void cp16(uint32_t saddr, const void* g) {
    asm volatile("cp.async.cg.shared.global [%0], [%1], 16;" :: "r"(saddr), "l"(g));
}
#define CP_COMMIT() asm volatile("cp.async.commit_group;" ::: "memory")
#define CP_WAIT1()  asm volatile("cp.async.wait_group 1;" ::: "memory")
#define CP_WAIT0()  asm volatile("cp.async.wait_group 0;" ::: "memory")

__device__ __forceinline__ void ldsm_x4(uint32_t (&r)[4], uint32_t addr) {
    asm volatile("ldmatrix.sync.aligned.m8n8.x4.shared.b16 {%0,%1,%2,%3}, [%4];"
        : "=r"(r[0]), "=r"(r[1]), "=r"(r[2]), "=r"(r[3]) : "r"(addr));
}
__device__ __forceinline__ void mma_f16(float (&d)[4], const uint32_t (&a)[4],
                                        uint32_t b0, uint32_t b1) {
    asm volatile("mma.sync.aligned.m16n8k16.row.col.f32.f16.f16.f32 "
        "{%0,%1,%2,%3}, {%4,%5,%6,%7}, {%8,%9}, {%0,%1,%2,%3};"
        : "+f"(d[0]), "+f"(d[1]), "+f"(d[2]), "+f"(d[3])
        : "r"(a[0]), "r"(a[1]), "r"(a[2]), "r"(a[3]), "r"(b0), "r"(b1));
}
__device__ __forceinline__ uint32_t sw128(uint32_t off) {
    return off ^ (((off >> 7) & 7) << 4);
}

// ==================== fp16 single-product GEMM ====================
// C[M,N] = A[M,K] @ B[N,K]^T, fp32 accumulate, both operands fp16.
// MODE 0: fused QKV. z: 0 -> Q (+biasQ), 1 -> K (+biasK), 2 -> V (+biasV, transposed)
// MODE 1: fp32 out (final PV), batch via z.
// MODE 2: fp16 out (scores), batch via z.
template <int MODE>
__global__ __launch_bounds__(256, 2)
void gemm_fp16(const __half* __restrict__ A, int lda,
               const __half* __restrict__ B, int ldb,
               const float* __restrict__ biasQ, const float* __restrict__ biasK, const float* __restrict__ biasV,
               float* __restrict__ Fo,
               __half* __restrict__ Oq, __half* __restrict__ Ok, __half* __restrict__ Ov,
               int ldo, int K, long long sA, long long sB, long long sO)
{
    extern __shared__ __align__(1024) char smem[];
    const uint32_t smb = smem_u32(smem);
    const int tid  = threadIdx.x;
    const int lane = tid & 31;
    const int wid  = tid >> 5;
    const int wm   = wid & 3;          // 4 warps along M
    const int wn   = wid >> 2;         // 2 warps along N
    const int z = blockIdx.z;
    const int rowBase = blockIdx.y * TMt;
    const int colBase = blockIdx.x * TNt;

    const __half* Ap = A + sA * z + (long long)rowBase * lda;
    const __half* Bp = B + sB * z + (long long)colBase * ldb;

    auto load_stage = [&](int st, int kt) {
        const int k0 = kt * TKt;
        const uint32_t sb = smb + st * STAGE_BYTES;
#pragma unroll
        for (int i = 0; i < 4; i++) {
            const int c  = tid + i * 256;      // 0..1023
            const int r  = c >> 3;
            const int cc = c & 7;
            const uint32_t sw = sw128((uint32_t)(r * 128 + cc * 16));
            cp16(sb + OFF_A + sw, Ap + (long long)r * lda + k0 + cc * 8);
            cp16(sb + OFF_B + sw, Bp + (long long)r * ldb + k0 + cc * 8);
        }
        CP_COMMIT();
    };

    float acc[2][8][4];
#pragma unroll
    for (int a = 0; a < 2; a++)
#pragma unroll
        for (int b = 0; b < 8; b++)
#pragma unroll
            for (int c = 0; c < 4; c++) acc[a][b][c] = 0.f;

    const int nk = K / TKt;
    load_stage(0, 0);
    load_stage(1, 1);

    for (int t = 0; t < nk; t++) {
        if (t + 1 < nk) { CP_WAIT1(); } else { CP_WAIT0(); }
        __syncthreads();
        if (t + 2 < nk) load_stage((t + 2) % NSTAGE, t + 2);

        const uint32_t sb = smb + (t % NSTAGE) * STAGE_BYTES;
#pragma unroll
        for (int kk = 0; kk < TKt; kk += 16) {
            uint32_t af[2][4], bf[4][4];
#pragma unroll
            for (int mt = 0; mt < 2; mt++) {
                const int r = wm * 32 + mt * 16 + (lane & 15);
                const uint32_t sw = sw128((uint32_t)(r * 128 + kk * 2 + ((lane >> 4) << 4)));
                ldsm_x4(af[mt], sb + OFF_A + sw);
            }
#pragma unroll
            for (int np = 0; np < 4; np++) {
                const int r = wn * 64 + np * 16 + (lane & 7) + ((lane >> 4) << 3);
                const uint32_t sw = sw128((uint32_t)(r * 128 + kk * 2 + (((lane >> 3) & 1) << 4)));
                ldsm_x4(bf[np], sb + OFF_B + sw);
            }
#pragma unroll
            for (int mt = 0; mt < 2; mt++)
#pragma unroll
                for (int np = 0; np < 4; np++) {
                    mma_f16(acc[mt][np * 2 + 0], af[mt], bf[np][0], bf[np][1]);
                    mma_f16(acc[mt][np * 2 + 1], af[mt], bf[np][2], bf[np][3]);
                }
        }
    }

    // ---------------- epilogue ----------------
    const int mB = wm * 32;
    const int nB = wn * 64;

    if (MODE == 1) {
        // fp32 out (final)
#pragma unroll
        for (int mt = 0; mt < 2; mt++)
#pragma unroll
            for (int nt = 0; nt < 8; nt++)
#pragma unroll
                for (int h = 0; h < 2; h++) {
                    const int m = rowBase + mB + mt * 16 + (lane >> 2) + h * 8;
                    const int n = colBase + nB + nt * 8 + ((lane & 3) << 1);
                    float2 fv;
                    fv.x = acc[mt][nt][h * 2 + 0];
                    fv.y = acc[mt][nt][h * 2 + 1];
                    *(float2*)(Fo + sO * z + (long long)m * ldo + n) = fv;
                }
    } else if (MODE == 2) {
        // fp16 out (scores)
#pragma unroll
        for (int mt = 0; mt < 2; mt++)
#pragma unroll
            for (int nt = 0; nt < 8; nt++)
#pragma unroll
                for (int h = 0; h < 2; h++) {
                    const int m = rowBase + mB + mt * 16 + (lane >> 2) + h * 8;
                    const int n = colBase + nB + nt * 8 + ((lane & 3) << 1);
                    __half2 hv;
                    hv.x = __float2half_rn(acc[mt][nt][h * 2 + 0]);
                    hv.y = __float2half_rn(acc[mt][nt][h * 2 + 1]);
                    *(__half2*)(Oq + sO * z + (long long)m * ldo + n) = hv;
                }
    } else if (z != 2) {
        // Q or K: fp16 row-major (+bias)
        const float* bias = (z == 0) ? biasQ : biasK;
        __half* O = (z == 0) ? Oq : Ok;
#pragma unroll
        for (int mt = 0; mt < 2; mt++)
#pragma unroll
            for (int nt = 0; nt < 8; nt++)
#pragma unroll
                for (int h = 0; h < 2; h++) {
                    const int m = rowBase + mB + mt * 16 + (lane >> 2) + h * 8;
                    const int n = colBase + nB + nt * 8 + ((lane & 3) << 1);
                    __half2 hv;
                    hv.x = __float2half_rn(acc[mt][nt][h * 2 + 0] + __ldg(&bias[n]));
                    hv.y = __float2half_rn(acc[mt][nt][h * 2 + 1] + __ldg(&bias[n + 1]));
                    *(__half2*)(O + (long long)m * DIM + n) = hv;
                }
    } else {
        // V: fp16, transposed per batch via smem bounce
        __half* Th = (__half*)smem;     // [128 n][136 m]
        __syncthreads();
#pragma unroll
        for (int mt = 0; mt < 2; mt++)
#pragma unroll
            for (int nt = 0; nt < 8; nt++)
#pragma unroll
                for (int h = 0; h < 2; h++) {
                    const int ml = mB + mt * 16 + (lane >> 2) + h * 8;
                    const int nl = nB + nt * 8 + ((lane & 3) << 1);
#pragma unroll
                    for (int j = 0; j < 2; j++) {
                        float v = acc[mt][nt][h * 2 + j] + __ldg(&biasV[colBase + nl + j]);
                        Th[(nl + j) * 136 + ml] = __float2half_rn(v);
                    }
                }
        __syncthreads();
        const int b   = rowBase >> 11;
        const int pos = rowBase & (SEQ - 1);
        const long long bb = (long long)b * DIM * SEQ + pos;
        for (int c = tid; c < 128 * 16; c += 256) {
            const int nr = c >> 4;
            const int cc = c & 15;
            const long long go = bb + (long long)(colBase + nr) * SEQ + cc * 8;
            *(uint4*)(Ov + go) = *(uint4*)(Th + nr * 136 + cc * 8);
        }
    }
}

// ---------------- prep kernels ----------------
// fp32 -> fp16 convert
__global__ void cvt_kernel(const float* __restrict__ src, __half* __restrict__ dst, long long n2)
{
    const long long stride = (long long)gridDim.x * blockDim.x;
    for (long long i = (long long)blockIdx.x * blockDim.x + threadIdx.x; i < n2; i += stride) {
        const float2 a = ((const float2*)src)[i];
        __half2 h;
        h.x = __float2half_rn(a.x);
        h.y = __float2half_rn(a.y);
        ((__half2*)dst)[i] = h;
    }
}

// batched transpose: z selects which W; Wt[n][k] = W[k][n], fp32 -> fp16
__global__ void wtrans_kernel(const float* __restrict__ W0, const float* __restrict__ W1,
                              const float* __restrict__ W2, __half* __restrict__ T16)
{
    const int z = blockIdx.z;
    const float* W = (z == 0) ? W0 : (z == 1) ? W1 : W2;
    __half* T = T16 + (long long)z * DIM * DIM;

    __shared__ float t[32][33];
    const int x = blockIdx.x * 32 + threadIdx.x;
    const int y0 = blockIdx.y * 32;
#pragma unroll
    for (int i = 0; i < 32; i += 8)
        t[threadIdx.y + i][threadIdx.x] = W[(long long)(y0 + threadIdx.y + i) * DIM + x];
    __syncthreads();
#pragma unroll
    for (int i = 0; i < 32; i += 8) {
        const float val = t[threadIdx.x][threadIdx.y + i];
        const int n = blockIdx.x * 32 + threadIdx.y + i;
        const int k = y0 + threadIdx.x;
        T[(long long)n * DIM + k] = __float2half_rn(val);
    }
}

// row softmax on fp16 scores (with 1/sqrt(D) scale) -> fp16 probs
__global__ void softmax_kernel(const __half* __restrict__ S16, __half* __restrict__ P16)
{
    const long long row = blockIdx.x;
    const __half2* p2 = (const __half2*)(S16 + row * (long long)SEQ);
    const int t = threadIdx.x;   // 256 threads, 4 half2 each

    __shared__ float sh[32];
    const float scale = 0.03125f;

    float v[8];
    float mx = -INFINITY;
#pragma unroll
    for (int i = 0; i < 4; i++) {
        const __half2 h = p2[t + i * 256];
        v[i * 2 + 0] = __half2float(h.x) * scale;
        v[i * 2 + 1] = __half2float(h.y) * scale;
        mx = fmaxf(mx, fmaxf(v[i * 2], v[i * 2 + 1]));
    }
#pragma unroll
    for (int o = 16; o; o >>= 1) mx = fmaxf(mx, __shfl_xor_sync(0xffffffffu, mx, o));
    if ((t & 31) == 0) sh[t >> 5] = mx;
    __syncthreads();
    if (t == 0) {
        float m = sh[0];
#pragma unroll
        for (int w = 1; w < 8; w++) m = fmaxf(m, sh[w]);
        sh[0] = m;
    }
    __syncthreads();
    mx = sh[0];

    float sum = 0.f;
#pragma unroll
    for (int i = 0; i < 8; i++) {
        v[i] = __expf(v[i] - mx);
        sum += v[i];
    }
#pragma unroll
    for (int o = 16; o; o >>= 1) sum += __shfl_xor_sync(0xffffffffu, sum, o);
    __syncthreads();
    if ((t & 31) == 0) sh[t >> 5] = sum;
    __syncthreads();
    if (t == 0) {
        float s = 0.f;
#pragma unroll
        for (int w = 0; w < 8; w++) s += sh[w];
        sh[0] = s;
    }
    __syncthreads();
    const float inv = 1.0f / sh[0];

    __half2* o2 = (__half2*)(P16 + row * (long long)SEQ);
#pragma unroll
    for (int i = 0; i < 4; i++) {
        __half2 h;
        h.x = __float2half_rn(v[i * 2 + 0] * inv);
        h.y = __float2half_rn(v[i * 2 + 1] * inv);
        o2[t + i * 256] = h;
    }
}

// ---------------- launch ----------------
extern "C" void kernel_launch(void* const* d_in, const int* in_sizes, int n_in,
                              void* d_out, int out_size)
{
    const float* x  = (const float*)d_in[0];
    const float* Wq = (const float*)d_in[1];
    const float* bq = (const float*)d_in[2];
    const float* Wk = (const float*)d_in[3];
    const float* bk = (const float*)d_in[4];
    const float* Wv = (const float*)d_in[5];
    const float* bv = (const float*)d_in[6];
    float* out = (float*)d_out;

    __half *x16, *wt16, *q16, *k16, *vt16, *s16, *p16;
    cudaGetSymbolAddress((void**)&x16,  g_x16);
    cudaGetSymbolAddress((void**)&wt16, g_wt16);
    cudaGetSymbolAddress((void**)&q16,  g_q16);
    cudaGetSymbolAddress((void**)&k16,  g_k16);
    cudaGetSymbolAddress((void**)&vt16, g_vt16);
    cudaGetSymbolAddress((void**)&s16,  g_s16);
    cudaGetSymbolAddress((void**)&p16,  g_p16);

    cudaFuncSetAttribute(gemm_fp16<0>, cudaFuncAttributeMaxDynamicSharedMemorySize, SMEM_TOTAL);
    cudaFuncSetAttribute(gemm_fp16<1>, cudaFuncAttributeMaxDynamicSharedMemorySize, SMEM_TOTAL);
    cudaFuncSetAttribute(gemm_fp16<2>, cudaFuncAttributeMaxDynamicSharedMemorySize, SMEM_TOTAL);

    // prep: convert x -> fp16, batched transpose W -> fp16
    cvt_kernel<<<4096, 256>>>(x, x16, (long long)BN_ROWS * DIM / 2);
    {
        dim3 g(DIM / 32, DIM / 32, 3), b(32, 8);
        wtrans_kernel<<<g, b>>>(Wq, Wk, Wv, wt16);
    }

    const dim3 blk(256);
    const long long sQK = (long long)SEQ * DIM;
    const long long sSS = (long long)SEQ * SEQ;

    // fused QKV projections
    {
        dim3 g(DIM / TNt, BN_ROWS / TMt, 3);   // (8, 128, 3)
        gemm_fp16<0><<<g, blk, SMEM_TOTAL>>>(x16, DIM, wt16, DIM,
                                             bq, bk, bv, nullptr,
                                             q16, k16, vt16,
                                             DIM, DIM, 0, (long long)DIM * DIM, 0);
    }
    // scores = Q @ K^T  (fp16 out)
    {
        dim3 g(SEQ / TNt, SEQ / TMt, BATCH);   // (16, 16, 8)
        gemm_fp16<2><<<g, blk, SMEM_TOTAL>>>(q16, DIM, k16, DIM,
                                             nullptr, nullptr, nullptr, nullptr,
                                             s16, nullptr, nullptr,
                                             SEQ, DIM, sQK, sQK, sSS);
    }
    // softmax fp16 -> fp16 P
    softmax_kernel<<<BATCH * SEQ, 256>>>(s16, p16);
    // out = P @ V   (V^T, K=SEQ, fp32 out)
    {
        dim3 g(DIM / TNt, SEQ / TMt, BATCH);   // (8, 16, 8)
        gemm_fp16<1><<<g, blk, SMEM_TOTAL>>>(p16, SEQ, vt16, SEQ,
                                             nullptr, nullptr, nullptr, out,
                                             nullptr, nullptr, nullptr,
                                             DIM, SEQ, sSS, (long long)DIM * SEQ, sQK);
    }
}

// round 11
// speedup vs baseline: 2.8403x; 1.0299x over previous
#include <cuda_runtime.h>
#include <cuda_fp16.h>
#include <cstdint>
#include <math.h>

#define BATCH 8
#define SEQ   2048
#define DIM   1024
#define BN_ROWS (BATCH * SEQ)     // 16384

// ---------------- tile config ----------------
#define TMt 128
#define TNt 128
#define TKt 64                     // fp16 elems per k-chunk (128B rows, SW128)

static constexpr int OFF_A = 0;
static constexpr int OFF_B = 16384;
static constexpr int STAGE_BYTES = 32768;
static constexpr int NSTAGE = 3;
static constexpr int SMEM_TOTAL = NSTAGE * STAGE_BYTES;  // 98304 -> 2 CTAs/SM

// ---------------- scratch (__device__ globals; no allocs allowed) --------------
__device__ __half g_x16[(long long)BN_ROWS * DIM];       // x fp16
__device__ __half g_wt16[3u * DIM * DIM];                // W^T fp16 (q,k,v)
__device__ __half g_q16[(long long)BN_ROWS * DIM];       // Q fp16
__device__ __half g_k16[(long long)BN_ROWS * DIM];       // K fp16
__device__ __half g_vt16[(long long)BATCH * DIM * SEQ];  // V^T fp16 [b][dim][seq]
__device__ __half g_p16[(long long)BATCH * SEQ * SEQ];   // P = exp(s/32), fp16 (unnormalized)
__device__ float  g_rowsum[BN_ROWS];                     // per-q-row sum of exp

// ---------------- PTX helpers ----------------
__device__ __forceinline__ uint32_t smem_u32(const void* p) {
    uint32_t a;
    asm("{ .reg .u64 t; cvta.to.shared.u64 t, %1; cvt.u32.u64 %0, t; }" : "=r"(a) : "l"(p));
    return a;
}
__device__ __forceinline__ void cp16(uint32_t saddr, const void* g) {
    asm volatile("cp.async.cg.shared.global [%0], [%1], 16;" :: "r"(saddr), "l"(g));
}
#define CP_COMMIT() asm volatile("cp.async.commit_group;" ::: "memory")
#define CP_WAIT1()  asm volatile("cp.async.wait_group 1;" ::: "memory")
#define CP_WAIT0()  asm volatile("cp.async.wait_group 0;" ::: "memory")

__device__ __forceinline__ void ldsm_x4(uint32_t (&r)[4], uint32_t addr) {
    asm volatile("ldmatrix.sync.aligned.m8n8.x4.shared.b16 {%0,%1,%2,%3}, [%4];"
        : "=r"(r[0]), "=r"(r[1]), "=r"(r[2]), "=r"(r[3]) : "r"(addr));
}
__device__ __forceinline__ void mma_f16(float (&d)[4], const uint32_t (&a)[4],
                                        uint32_t b0, uint32_t b1) {
    asm volatile("mma.sync.aligned.m16n8k16.row.col.f32.f16.f16.f32 "
        "{%0,%1,%2,%3}, {%4,%5,%6,%7}, {%8,%9}, {%0,%1,%2,%3};"
        : "+f"(d[0]), "+f"(d[1]), "+f"(d[2]), "+f"(d[3])
        : "r"(a[0]), "r"(a[1]), "r"(a[2]), "r"(a[3]), "r"(b0), "r"(b1));
}
__device__ __forceinline__ uint32_t sw128(uint32_t off) {
    return off ^ (((off >> 7) & 7) << 4);
}

// ==================== fp16 single-product GEMM ====================
// C[M,N] = A[M,K] @ B[N,K]^T, fp32 accumulate, both operands fp16.
// MODE 0: fused QKV. z: 0 -> Q (+biasQ), 1 -> K (+biasK), 2 -> V (+biasV, transposed)
// MODE 1: final PV: fp32 out scaled by 1/rowsum[m] (softmax normalization)
// MODE 2: scores: store exp(s/32) as fp16 P + atomic row-sums of exp
template <int MODE>
__global__ __launch_bounds__(256, 2)
void gemm_fp16(const __half* __restrict__ A, int lda,
               const __half* __restrict__ B, int ldb,
               const float* __restrict__ biasQ, const float* __restrict__ biasK, const float* __restrict__ biasV,
               float* __restrict__ Fo, float* __restrict__ Rsum,
               __half* __restrict__ Oq, __half* __restrict__ Ok, __half* __restrict__ Ov,
               int ldo, int K, long long sA, long long sB, long long sO)
{
    extern __shared__ __align__(1024) char smem[];
    const uint32_t smb = smem_u32(smem);
    const int tid  = threadIdx.x;
    const int lane = tid & 31;
    const int wid  = tid >> 5;
    const int wm   = wid & 3;          // 4 warps along M
    const int wn   = wid >> 2;         // 2 warps along N
    const int z = blockIdx.z;
    const int rowBase = blockIdx.y * TMt;
    const int colBase = blockIdx.x * TNt;

    const __half* Ap = A + sA * z + (long long)rowBase * lda;
    const __half* Bp = B + sB * z + (long long)colBase * ldb;

    auto load_stage = [&](int st, int kt) {
        const int k0 = kt * TKt;
        const uint32_t sb = smb + st * STAGE_BYTES;
#pragma unroll
        for (int i = 0; i < 4; i++) {
            const int c  = tid + i * 256;      // 0..1023
            const int r  = c >> 3;
            const int cc = c & 7;
            const uint32_t sw = sw128((uint32_t)(r * 128 + cc * 16));
            cp16(sb + OFF_A + sw, Ap + (long long)r * lda + k0 + cc * 8);
            cp16(sb + OFF_B + sw, Bp + (long long)r * ldb + k0 + cc * 8);
        }
        CP_COMMIT();
    };

    float acc[2][8][4];
#pragma unroll
    for (int a = 0; a < 2; a++)
#pragma unroll
        for (int b = 0; b < 8; b++)
#pragma unroll
            for (int c = 0; c < 4; c++) acc[a][b][c] = 0.f;

    const int nk = K / TKt;
    load_stage(0, 0);
    load_stage(1, 1);

    for (int t = 0; t < nk; t++) {
        if (t + 1 < nk) { CP_WAIT1(); } else { CP_WAIT0(); }
        __syncthreads();
        if (t + 2 < nk) load_stage((t + 2) % NSTAGE, t + 2);

        const uint32_t sb = smb + (t % NSTAGE) * STAGE_BYTES;
#pragma unroll
        for (int kk = 0; kk < TKt; kk += 16) {
            uint32_t af[2][4], bf[4][4];
#pragma unroll
            for (int mt = 0; mt < 2; mt++) {
                const int r = wm * 32 + mt * 16 + (lane & 15);
                const uint32_t sw = sw128((uint32_t)(r * 128 + kk * 2 + ((lane >> 4) << 4)));
                ldsm_x4(af[mt], sb + OFF_A + sw);
            }
#pragma unroll
            for (int np = 0; np < 4; np++) {
                const int r = wn * 64 + np * 16 + (lane & 7) + ((lane >> 4) << 3);
                const uint32_t sw = sw128((uint32_t)(r * 128 + kk * 2 + (((lane >> 3) & 1) << 4)));
                ldsm_x4(bf[np], sb + OFF_B + sw);
            }
#pragma unroll
            for (int mt = 0; mt < 2; mt++)
#pragma unroll
                for (int np = 0; np < 4; np++) {
                    mma_f16(acc[mt][np * 2 + 0], af[mt], bf[np][0], bf[np][1]);
                    mma_f16(acc[mt][np * 2 + 1], af[mt], bf[np][2], bf[np][3]);
                }
        }
    }

    // ---------------- epilogue ----------------
    const int mB = wm * 32;
    const int nB = wn * 64;

    if (MODE == 1) {
        // final PV: scale each row by 1/rowsum (deferred softmax normalization)
#pragma unroll
        for (int mt = 0; mt < 2; mt++)
#pragma unroll
            for (int h = 0; h < 2; h++) {
                const int m = rowBase + mB + mt * 16 + (lane >> 2) + h * 8;
                const float inv = 1.0f / __ldg(&Rsum[z * SEQ + m]);
#pragma unroll
                for (int nt = 0; nt < 8; nt++) {
                    const int n = colBase + nB + nt * 8 + ((lane & 3) << 1);
                    float2 fv;
                    fv.x = acc[mt][nt][h * 2 + 0] * inv;
                    fv.y = acc[mt][nt][h * 2 + 1] * inv;
                    *(float2*)(Fo + sO * z + (long long)m * ldo + n) = fv;
                }
            }
    } else if (MODE == 2) {
        // scores: e = exp(s/32) stored fp16, row-sums accumulated atomically
        const float scale = 0.03125f;
#pragma unroll
        for (int mt = 0; mt < 2; mt++)
#pragma unroll
            for (int h = 0; h < 2; h++) {
                const int m = rowBase + mB + mt * 16 + (lane >> 2) + h * 8;
                float part = 0.f;
#pragma unroll
                for (int nt = 0; nt < 8; nt++) {
                    const int n = colBase + nB + nt * 8 + ((lane & 3) << 1);
                    const float e0 = __expf(acc[mt][nt][h * 2 + 0] * scale);
                    const float e1 = __expf(acc[mt][nt][h * 2 + 1] * scale);
                    part += e0 + e1;
                    __half2 hv;
                    hv.x = __float2half_rn(e0);
                    hv.y = __float2half_rn(e1);
                    *(__half2*)(Oq + sO * z + (long long)m * ldo + n) = hv;
                }
                // reduce across the 4 lanes sharing this row (lane&3 varies)
                part += __shfl_xor_sync(0xffffffffu, part, 1);
                part += __shfl_xor_sync(0xffffffffu, part, 2);
                if ((lane & 3) == 0)
                    atomicAdd(&Rsum[z * SEQ + m], part);
            }
    } else if (z != 2) {
        // Q or K: fp16 row-major (+bias)
        const float* bias = (z == 0) ? biasQ : biasK;
        __half* O = (z == 0) ? Oq : Ok;
#pragma unroll
        for (int mt = 0; mt < 2; mt++)
#pragma unroll
            for (int nt = 0; nt < 8; nt++)
#pragma unroll
                for (int h = 0; h < 2; h++) {
                    const int m = rowBase + mB + mt * 16 + (lane >> 2) + h * 8;
                    const int n = colBase + nB + nt * 8 + ((lane & 3) << 1);
                    __half2 hv;
                    hv.x = __float2half_rn(acc[mt][nt][h * 2 + 0] + __ldg(&bias[n]));
                    hv.y = __float2half_rn(acc[mt][nt][h * 2 + 1] + __ldg(&bias[n + 1]));
                    *(__half2*)(O + (long long)m * DIM + n) = hv;
                }
    } else {
        // V: fp16, transposed per batch via smem bounce
        __half* Th = (__half*)smem;     // [128 n][136 m]
        __syncthreads();
#pragma unroll
        for (int mt = 0; mt < 2; mt++)
#pragma unroll
            for (int nt = 0; nt < 8; nt++)
#pragma unroll
                for (int h = 0; h < 2; h++) {
                    const int ml = mB + mt * 16 + (lane >> 2) + h * 8;
                    const int nl = nB + nt * 8 + ((lane & 3) << 1);
#pragma unroll
                    for (int j = 0; j < 2; j++) {
                        float v = acc[mt][nt][h * 2 + j] + __ldg(&biasV[colBase + nl + j]);
                        Th[(nl + j) * 136 + ml] = __float2half_rn(v);
                    }
                }
        __syncthreads();
        const int b   = rowBase >> 11;
        const int pos = rowBase & (SEQ - 1);
        const long long bb = (long long)b * DIM * SEQ + pos;
        for (int c = tid; c < 128 * 16; c += 256) {
            const int nr = c >> 4;
            const int cc = c & 15;
            const long long go = bb + (long long)(colBase + nr) * SEQ + cc * 8;
            *(uint4*)(Ov + go) = *(uint4*)(Th + nr * 136 + cc * 8);
        }
    }
}

// ---------------- prep kernels ----------------
// fp32 -> fp16 convert (float4 vectorized)
__global__ void cvt_kernel(const float* __restrict__ src, __half* __restrict__ dst, long long n4)
{
    const long long stride = (long long)gridDim.x * blockDim.x;
    for (long long i = (long long)blockIdx.x * blockDim.x + threadIdx.x; i < n4; i += stride) {
        const float4 a = ((const float4*)src)[i];
        __half2 h0, h1;
        h0.x = __float2half_rn(a.x);
        h0.y = __float2half_rn(a.y);
        h1.x = __float2half_rn(a.z);
        h1.y = __float2half_rn(a.w);
        ((__half2*)dst)[i * 2 + 0] = h0;
        ((__half2*)dst)[i * 2 + 1] = h1;
    }
}

// batched transpose: z selects which W; Wt[n][k] = W[k][n], fp32 -> fp16
__global__ void wtrans_kernel(const float* __restrict__ W0, const float* __restrict__ W1,
                              const float* __restrict__ W2, __half* __restrict__ T16)
{
    const int z = blockIdx.z;
    const float* W = (z == 0) ? W0 : (z == 1) ? W1 : W2;
    __half* T = T16 + (long long)z * DIM * DIM;

    __shared__ float t[32][33];
    const int x = blockIdx.x * 32 + threadIdx.x;
    const int y0 = blockIdx.y * 32;
#pragma unroll
    for (int i = 0; i < 32; i += 8)
        t[threadIdx.y + i][threadIdx.x] = W[(long long)(y0 + threadIdx.y + i) * DIM + x];
    __syncthreads();
#pragma unroll
    for (int i = 0; i < 32; i += 8) {
        const float val = t[threadIdx.x][threadIdx.y + i];
        const int n = blockIdx.x * 32 + threadIdx.y + i;
        const int k = y0 + threadIdx.x;
        T[(long long)n * DIM + k] = __float2half_rn(val);
    }
}

// ---------------- launch ----------------
extern "C" void kernel_launch(void* const* d_in, const int* in_sizes, int n_in,
                              void* d_out, int out_size)
{
    const float* x  = (const float*)d_in[0];
    const float* Wq = (const float*)d_in[1];
    const float* bq = (const float*)d_in[2];
    const float* Wk = (const float*)d_in[3];
    const float* bk = (const float*)d_in[4];
    const float* Wv = (const float*)d_in[5];
    const float* bv = (const float*)d_in[6];
    float* out = (float*)d_out;

    __half *x16, *wt16, *q16, *k16, *vt16, *p16;
    float* rsum;
    cudaGetSymbolAddress((void**)&x16,  g_x16);
    cudaGetSymbolAddress((void**)&wt16, g_wt16);
    cudaGetSymbolAddress((void**)&q16,  g_q16);
    cudaGetSymbolAddress((void**)&k16,  g_k16);
    cudaGetSymbolAddress((void**)&vt16, g_vt16);
    cudaGetSymbolAddress((void**)&p16,  g_p16);
    cudaGetSymbolAddress((void**)&rsum, g_rowsum);

    cudaFuncSetAttribute(gemm_fp16<0>, cudaFuncAttributeMaxDynamicSharedMemorySize, SMEM_TOTAL);
    cudaFuncSetAttribute(gemm_fp16<1>, cudaFuncAttributeMaxDynamicSharedMemorySize, SMEM_TOTAL);
    cudaFuncSetAttribute(gemm_fp16<2>, cudaFuncAttributeMaxDynamicSharedMemorySize, SMEM_TOTAL);

    // zero row-sum accumulators (graph-capturable async memset)
    cudaMemsetAsync(rsum, 0, BN_ROWS * sizeof(float));

    // prep: convert x -> fp16 (float4), batched transpose W -> fp16
    cvt_kernel<<<2048, 256>>>(x, x16, (long long)BN_ROWS * DIM / 4);
    {
        dim3 g(DIM / 32, DIM / 32, 3), b(32, 8);
        wtrans_kernel<<<g, b>>>(Wq, Wk, Wv, wt16);
    }

    const dim3 blk(256);
    const long long sQK = (long long)SEQ * DIM;
    const long long sSS = (long long)SEQ * SEQ;

    // fused QKV projections
    {
        dim3 g(DIM / TNt, BN_ROWS / TMt, 3);   // (8, 128, 3)
        gemm_fp16<0><<<g, blk, SMEM_TOTAL>>>(x16, DIM, wt16, DIM,
                                             bq, bk, bv, nullptr, nullptr,
                                             q16, k16, vt16,
                                             DIM, DIM, 0, (long long)DIM * DIM, 0);
    }
    // scores: P = exp(QK^T/32) fp16 + row sums (softmax fused, normalization deferred)
    {
        dim3 g(SEQ / TNt, SEQ / TMt, BATCH);   // (16, 16, 8)
        gemm_fp16<2><<<g, blk, SMEM_TOTAL>>>(q16, DIM, k16, DIM,
                                             nullptr, nullptr, nullptr, nullptr, rsum,
                                             p16, nullptr, nullptr,
                                             SEQ, DIM, sQK, sQK, sSS);
    }
    // out = (P @ V) / rowsum   (V^T, K=SEQ, fp32 out)
    {
        dim3 g(DIM / TNt, SEQ / TMt, BATCH);   // (8, 16, 8)
        gemm_fp16<1><<<g, blk, SMEM_TOTAL>>>(p16, SEQ, vt16, SEQ,
                                             nullptr, nullptr, nullptr, out, rsum,
                                             nullptr, nullptr, nullptr,
                                             DIM, SEQ, sSS, (long long)DIM * SEQ, sQK);
    }
}